// round 1
// baseline (speedup 1.0000x reference)
#include <cuda_runtime.h>
#include <math.h>
#include <stddef.h>

// Problem constants
#define Bq 2
#define Tt 1024
#define Dd 768
#define Hh 12
#define Ll 6
#define Vv 50257
#define HS 64
#define Mm (Bq*Tt)      // 2048 tokens
#define DFF (4*Dd)      // 3072

// ---------------- scratch (device globals; no allocations allowed) ----------
__device__ float g_x  [Mm*Dd];                       // activations [B*T, D]
__device__ float g_tmp[Mm*Dd];                       // residual branch output
__device__ float g_q  [Mm*Dd];                       // [B,H,T,HS]
__device__ float g_k  [Mm*Dd];
__device__ float g_v  [Mm*Dd];
__device__ float g_o  [Mm*Dd];                       // attn out, [B,T,D]
__device__ float g_h1 [Mm*DFF];                      // MLP hidden
__device__ float g_s  [(size_t)Bq*Hh*Tt*Tt];         // attention scores/probs

// ---------------- helpers ---------------------------------------------------
__device__ __forceinline__ float block_reduce_sum(float v, float* sh) {
    int tid = threadIdx.x;
    #pragma unroll
    for (int o = 16; o > 0; o >>= 1) v += __shfl_xor_sync(0xffffffffu, v, o);
    if ((tid & 31) == 0) sh[tid >> 5] = v;
    __syncthreads();
    if (tid < 32) {
        float x = (tid < (int)(blockDim.x >> 5)) ? sh[tid] : 0.f;
        #pragma unroll
        for (int o = 4; o > 0; o >>= 1) x += __shfl_xor_sync(0xffffffffu, x, o);
        if (tid == 0) sh[0] = x;
    }
    __syncthreads();
    float r = sh[0];
    __syncthreads();
    return r;
}

__device__ __forceinline__ float block_reduce_max(float v, float* sh) {
    int tid = threadIdx.x;
    #pragma unroll
    for (int o = 16; o > 0; o >>= 1) v = fmaxf(v, __shfl_xor_sync(0xffffffffu, v, o));
    if ((tid & 31) == 0) sh[tid >> 5] = v;
    __syncthreads();
    if (tid < 32) {
        float x = (tid < (int)(blockDim.x >> 5)) ? sh[tid] : -1e30f;
        #pragma unroll
        for (int o = 4; o > 0; o >>= 1) x = fmaxf(x, __shfl_xor_sync(0xffffffffu, x, o));
        if (tid == 0) sh[0] = x;
    }
    __syncthreads();
    float r = sh[0];
    __syncthreads();
    return r;
}

// ---------------- embedding -------------------------------------------------
__global__ void embed_kernel(const int* __restrict__ idx,
                             const float* __restrict__ tok_emb,
                             const float* __restrict__ pos_emb) {
    int m = blockIdx.x;            // token row 0..2047
    int t = m % Tt;
    int tok = idx[m];
    const float* te = tok_emb + (size_t)tok * Dd;
    const float* pe = pos_emb + (size_t)t * Dd;
    float* x = g_x + (size_t)m * Dd;
    for (int c = threadIdx.x; c < Dd; c += blockDim.x)
        x[c] = te[c] + pe[c];
}

// ---------------- generic SGEMM: C = A(MxK) @ W(KxN) + bias, opt ReLU -------
// 128x128 tile, BK=8, 256 threads, 8x8 per thread.
// Requires: M%128==0, K%8==0, K%4==0 (float4 A loads). N handled with guards;
// nAligned selects the float4 B path (N%4==0).
__global__ void sgemm_bias(const float* __restrict__ A,
                           const float* __restrict__ W,
                           const float* __restrict__ bias,
                           float* __restrict__ C,
                           int M, int N, int K, int relu, int nAligned) {
    __shared__ float As[8][128];
    __shared__ float Bs[8][128];
    int tid  = threadIdx.x;
    int row0 = blockIdx.y * 128;
    int col0 = blockIdx.x * 128;
    int tx = tid & 15, ty = tid >> 4;

    float acc[8][8];
    #pragma unroll
    for (int i = 0; i < 8; i++)
        #pragma unroll
        for (int j = 0; j < 8; j++) acc[i][j] = 0.f;

    int am = tid >> 1, ak = (tid & 1) * 4;     // A: 128 rows x 8 k
    int bk = tid >> 5, bn = (tid & 31) * 4;    // B: 8 k x 128 n

    for (int k0 = 0; k0 < K; k0 += 8) {
        float4 av = *(const float4*)(A + (size_t)(row0 + am) * K + k0 + ak);
        As[ak + 0][am] = av.x; As[ak + 1][am] = av.y;
        As[ak + 2][am] = av.z; As[ak + 3][am] = av.w;

        int gn = col0 + bn;
        const float* wr = W + (size_t)(k0 + bk) * N;
        if (nAligned && gn + 3 < N) {
            float4 bv = *(const float4*)(wr + gn);
            Bs[bk][bn + 0] = bv.x; Bs[bk][bn + 1] = bv.y;
            Bs[bk][bn + 2] = bv.z; Bs[bk][bn + 3] = bv.w;
        } else {
            #pragma unroll
            for (int j = 0; j < 4; j++)
                Bs[bk][bn + j] = (gn + j < N) ? wr[gn + j] : 0.f;
        }
        __syncthreads();

        #pragma unroll
        for (int kk = 0; kk < 8; kk++) {
            float a[8], b[8];
            #pragma unroll
            for (int i = 0; i < 8; i++) a[i] = As[kk][ty * 8 + i];
            #pragma unroll
            for (int j = 0; j < 8; j++) b[j] = Bs[kk][tx * 8 + j];
            #pragma unroll
            for (int i = 0; i < 8; i++)
                #pragma unroll
                for (int j = 0; j < 8; j++) acc[i][j] += a[i] * b[j];
        }
        __syncthreads();
    }

    #pragma unroll
    for (int i = 0; i < 8; i++) {
        int r = row0 + ty * 8 + i;
        #pragma unroll
        for (int j = 0; j < 8; j++) {
            int c = col0 + tx * 8 + j;
            if (c < N) {
                float v = acc[i][j] + bias[c];
                if (relu) v = fmaxf(v, 0.f);
                C[(size_t)r * N + c] = v;
            }
        }
    }
}

// ---------------- per-head QKV: q[b,h,t,s] = sum_d x[b,t,d]*wq[l,h,d,s] -----
// grid (Mm/64, H, 3), block 256, 64x64 tile, BK=16, 4x4 per thread.
__global__ void qkv_kernel(const float* __restrict__ wq,
                           const float* __restrict__ wk,
                           const float* __restrict__ wv,
                           int layer) {
    int which = blockIdx.z;
    int h     = blockIdx.y;
    int row0  = blockIdx.x * 64;
    const float* Wb = (which == 0 ? wq : which == 1 ? wk : wv)
                      + ((size_t)layer * Hh + h) * Dd * HS;
    float* out = which == 0 ? g_q : which == 1 ? g_k : g_v;

    __shared__ float As[16][64];   // [k][m]
    __shared__ float Bs[16][64];   // [k][n]
    int tid = threadIdx.x;
    int tx = tid & 15, ty = tid >> 4;
    float acc[4][4];
    #pragma unroll
    for (int i = 0; i < 4; i++)
        #pragma unroll
        for (int j = 0; j < 4; j++) acc[i][j] = 0.f;

    int am = tid >> 2, ak = (tid & 3) * 4;   // 64 rows x 16 k
    int bk = tid >> 4, bn = (tid & 15) * 4;  // 16 k x 64 n

    for (int k0 = 0; k0 < Dd; k0 += 16) {
        float4 av = *(const float4*)(g_x + (size_t)(row0 + am) * Dd + k0 + ak);
        As[ak + 0][am] = av.x; As[ak + 1][am] = av.y;
        As[ak + 2][am] = av.z; As[ak + 3][am] = av.w;
        float4 bv = *(const float4*)(Wb + (size_t)(k0 + bk) * HS + bn);
        Bs[bk][bn + 0] = bv.x; Bs[bk][bn + 1] = bv.y;
        Bs[bk][bn + 2] = bv.z; Bs[bk][bn + 3] = bv.w;
        __syncthreads();
        #pragma unroll
        for (int kk = 0; kk < 16; kk++) {
            float a[4], b[4];
            #pragma unroll
            for (int i = 0; i < 4; i++) a[i] = As[kk][ty * 4 + i];
            #pragma unroll
            for (int j = 0; j < 4; j++) b[j] = Bs[kk][tx * 4 + j];
            #pragma unroll
            for (int i = 0; i < 4; i++)
                #pragma unroll
                for (int j = 0; j < 4; j++) acc[i][j] += a[i] * b[j];
        }
        __syncthreads();
    }

    #pragma unroll
    for (int i = 0; i < 4; i++) {
        int m = row0 + ty * 4 + i;
        int b = m / Tt, t = m % Tt;
        float* orow = out + (((size_t)(b * Hh + h) * Tt + t) * HS);
        #pragma unroll
        for (int j = 0; j < 4; j++) orow[tx * 4 + j] = acc[i][j];
    }
}

// ---------------- scores: S[bh,t,u] = 0.125 * dot(q[t,:], k[u,:]) -----------
// grid (T/64, T/64, B*H); causal tile skip when u-tile fully above diagonal.
__global__ void scores_kernel() {
    int u0 = blockIdx.x * 64;
    int t0 = blockIdx.y * 64;
    if (u0 > t0 + 63) return;     // entirely masked
    int bh = blockIdx.z;
    const float* qb = g_q + (size_t)bh * Tt * HS;
    const float* kb = g_k + (size_t)bh * Tt * HS;
    float* Sb = g_s + (size_t)bh * Tt * Tt;

    __shared__ float Qs[16][64];  // [s][t]
    __shared__ float Ks[16][64];  // [s][u]
    int tid = threadIdx.x;
    int tx = tid & 15, ty = tid >> 4;
    float acc[4][4];
    #pragma unroll
    for (int i = 0; i < 4; i++)
        #pragma unroll
        for (int j = 0; j < 4; j++) acc[i][j] = 0.f;

    int rl = tid >> 2, sc = (tid & 3) * 4;   // 64 rows x 16 s-chunk

    for (int s0 = 0; s0 < HS; s0 += 16) {
        float4 qv = *(const float4*)(qb + (size_t)(t0 + rl) * HS + s0 + sc);
        Qs[sc + 0][rl] = qv.x; Qs[sc + 1][rl] = qv.y;
        Qs[sc + 2][rl] = qv.z; Qs[sc + 3][rl] = qv.w;
        float4 kv = *(const float4*)(kb + (size_t)(u0 + rl) * HS + s0 + sc);
        Ks[sc + 0][rl] = kv.x; Ks[sc + 1][rl] = kv.y;
        Ks[sc + 2][rl] = kv.z; Ks[sc + 3][rl] = kv.w;
        __syncthreads();
        #pragma unroll
        for (int kk = 0; kk < 16; kk++) {
            float a[4], b[4];
            #pragma unroll
            for (int i = 0; i < 4; i++) a[i] = Qs[kk][ty * 4 + i];
            #pragma unroll
            for (int j = 0; j < 4; j++) b[j] = Ks[kk][tx * 4 + j];
            #pragma unroll
            for (int i = 0; i < 4; i++)
                #pragma unroll
                for (int j = 0; j < 4; j++) acc[i][j] += a[i] * b[j];
        }
        __syncthreads();
    }

    #pragma unroll
    for (int i = 0; i < 4; i++) {
        int t = t0 + ty * 4 + i;
        #pragma unroll
        for (int j = 0; j < 4; j++) {
            int u = u0 + tx * 4 + j;
            Sb[(size_t)t * Tt + u] = acc[i][j] * 0.125f;
        }
    }
}

// ---------------- row softmax with causal mask ------------------------------
// grid B*H*T blocks; zeros written for u>t (PV GEMM reads full tiles).
__global__ void softmax_kernel() {
    __shared__ float sh[8];
    int row = blockIdx.x;            // bh*T + t
    int t   = row % Tt;
    float* p = g_s + (size_t)row * Tt;
    int n = t + 1;
    int tid = threadIdx.x;

    float m = -1e30f;
    for (int u = tid; u < n; u += 256) m = fmaxf(m, p[u]);
    m = block_reduce_max(m, sh);

    float s = 0.f;
    for (int u = tid; u < n; u += 256) {
        float e = __expf(p[u] - m);
        p[u] = e;
        s += e;
    }
    s = block_reduce_sum(s, sh);
    float inv = 1.f / s;

    for (int u = tid; u < n; u += 256) p[u] *= inv;
    for (int u = n + tid; u < Tt; u += 256) p[u] = 0.f;
}

// ---------------- PV: O[b,t,h*HS+s] = sum_u P[t,u] * v[u,s] -----------------
// grid (1, T/64, B*H); K loop runs only over tiles with u0 <= t0+63.
__global__ void pv_kernel() {
    int bh = blockIdx.z;
    int t0 = blockIdx.y * 64;
    const float* Pb = g_s + (size_t)bh * Tt * Tt;
    const float* vb = g_v + (size_t)bh * Tt * HS;
    int b = bh / Hh, h = bh % Hh;

    __shared__ float Ps[16][64];  // [u][t]
    __shared__ float Vs[16][64];  // [u][s]
    int tid = threadIdx.x;
    int tx = tid & 15, ty = tid >> 4;
    float acc[4][4];
    #pragma unroll
    for (int i = 0; i < 4; i++)
        #pragma unroll
        for (int j = 0; j < 4; j++) acc[i][j] = 0.f;

    int tl = tid >> 2, uk = (tid & 3) * 4;   // P: 64 t-rows x 16 u
    int bu = tid >> 4, sn = (tid & 15) * 4;  // V: 16 u x 64 s

    for (int u0 = 0; u0 < t0 + 64; u0 += 16) {
        float4 pv = *(const float4*)(Pb + (size_t)(t0 + tl) * Tt + u0 + uk);
        Ps[uk + 0][tl] = pv.x; Ps[uk + 1][tl] = pv.y;
        Ps[uk + 2][tl] = pv.z; Ps[uk + 3][tl] = pv.w;
        float4 vv = *(const float4*)(vb + (size_t)(u0 + bu) * HS + sn);
        Vs[bu][sn + 0] = vv.x; Vs[bu][sn + 1] = vv.y;
        Vs[bu][sn + 2] = vv.z; Vs[bu][sn + 3] = vv.w;
        __syncthreads();
        #pragma unroll
        for (int kk = 0; kk < 16; kk++) {
            float a[4], b2[4];
            #pragma unroll
            for (int i = 0; i < 4; i++) a[i] = Ps[kk][ty * 4 + i];
            #pragma unroll
            for (int j = 0; j < 4; j++) b2[j] = Vs[kk][tx * 4 + j];
            #pragma unroll
            for (int i = 0; i < 4; i++)
                #pragma unroll
                for (int j = 0; j < 4; j++) acc[i][j] += a[i] * b2[j];
        }
        __syncthreads();
    }

    #pragma unroll
    for (int i = 0; i < 4; i++) {
        int t = t0 + ty * 4 + i;
        float* orow = g_o + ((size_t)(b * Tt + t) * Dd + h * HS);
        #pragma unroll
        for (int j = 0; j < 4; j++) orow[tx * 4 + j] = acc[i][j];
    }
}

// ---------------- fused residual add + LayerNorm (in place into g_x) --------
__global__ void addln_kernel(const float* __restrict__ add,
                             const float* __restrict__ gamma,
                             const float* __restrict__ beta) {
    __shared__ float sh[8];
    int m = blockIdx.x;
    float* x = g_x + (size_t)m * Dd;
    const float* a = add + (size_t)m * Dd;
    int tid = threadIdx.x;

    float v[3];
    float s = 0.f;
    #pragma unroll
    for (int i = 0; i < 3; i++) {
        int c = tid + i * 256;
        v[i] = x[c] + a[c];
        s += v[i];
    }
    s = block_reduce_sum(s, sh);
    float mean = s * (1.f / Dd);

    float q = 0.f;
    #pragma unroll
    for (int i = 0; i < 3; i++) {
        float d = v[i] - mean;
        q += d * d;
    }
    q = block_reduce_sum(q, sh);
    float rstd = rsqrtf(q * (1.f / Dd) + 1e-5f);

    #pragma unroll
    for (int i = 0; i < 3; i++) {
        int c = tid + i * 256;
        x[c] = (v[i] - mean) * rstd * gamma[c] + beta[c];
    }
}

// ---------------- host orchestration ----------------------------------------
extern "C" void kernel_launch(void* const* d_in, const int* in_sizes, int n_in,
                              void* d_out, int out_size) {
    const int*   idx     = (const int*)  d_in[0];
    const float* tok_emb = (const float*)d_in[1];
    const float* pos_emb = (const float*)d_in[2];
    const float* wq      = (const float*)d_in[3];
    const float* wk      = (const float*)d_in[4];
    const float* wv      = (const float*)d_in[5];
    const float* wproj   = (const float*)d_in[6];
    const float* bproj   = (const float*)d_in[7];
    const float* w1      = (const float*)d_in[8];
    const float* b1      = (const float*)d_in[9];
    const float* w2      = (const float*)d_in[10];
    const float* b2      = (const float*)d_in[11];
    const float* ln1_g   = (const float*)d_in[12];
    const float* ln1_b   = (const float*)d_in[13];
    const float* ln2_g   = (const float*)d_in[14];
    const float* ln2_b   = (const float*)d_in[15];
    const float* lm_w    = (const float*)d_in[16];
    const float* lm_b    = (const float*)d_in[17];
    float* out = (float*)d_out;

    float *p_x, *p_tmp, *p_o, *p_h1;
    cudaGetSymbolAddress((void**)&p_x,   g_x);
    cudaGetSymbolAddress((void**)&p_tmp, g_tmp);
    cudaGetSymbolAddress((void**)&p_o,   g_o);
    cudaGetSymbolAddress((void**)&p_h1,  g_h1);

    embed_kernel<<<Mm, 256>>>(idx, tok_emb, pos_emb);

    for (int l = 0; l < Ll; l++) {
        // QKV projections (per head)
        qkv_kernel<<<dim3(Mm / 64, Hh, 3), 256>>>(wq, wk, wv, l);
        // attention
        scores_kernel <<<dim3(Tt / 64, Tt / 64, Bq * Hh), 256>>>();
        softmax_kernel<<<Bq * Hh * Tt, 256>>>();
        pv_kernel     <<<dim3(1, Tt / 64, Bq * Hh), 256>>>();
        // output projection: tmp = o @ wproj[l] + bproj[l]
        sgemm_bias<<<dim3(Dd / 128, Mm / 128), 256>>>(
            p_o, wproj + (size_t)l * Dd * Dd, bproj + (size_t)l * Dd,
            p_tmp, Mm, Dd, Dd, 0, 1);
        // x = LN(x + tmp)
        addln_kernel<<<Mm, 256>>>(p_tmp, ln1_g + (size_t)l * Dd, ln1_b + (size_t)l * Dd);
        // MLP
        sgemm_bias<<<dim3(DFF / 128, Mm / 128), 256>>>(
            p_x, w1 + (size_t)l * Dd * DFF, b1 + (size_t)l * DFF,
            p_h1, Mm, DFF, Dd, 1, 1);
        sgemm_bias<<<dim3(Dd / 128, Mm / 128), 256>>>(
            p_h1, w2 + (size_t)l * DFF * Dd, b2 + (size_t)l * Dd,
            p_tmp, Mm, Dd, DFF, 0, 1);
        addln_kernel<<<Mm, 256>>>(p_tmp, ln2_g + (size_t)l * Dd, ln2_b + (size_t)l * Dd);
    }

    // logits = x @ lm_w + lm_b  -> [2048, 50257] fp32
    sgemm_bias<<<dim3((Vv + 127) / 128, Mm / 128), 256>>>(
        p_x, lm_w, lm_b, out, Mm, Vv, Dd, 0, 0);
}

// round 3
// speedup vs baseline: 2.4793x; 2.4793x over previous
#include <cuda_runtime.h>
#include <cuda_bf16.h>
#include <cstdint>
#include <math.h>
#include <stddef.h>

// Problem constants
#define Bq 2
#define Tt 1024
#define Dd 768
#define Hh 12
#define Ll 6
#define Vv 50257
#define HS 64
#define Mm (Bq*Tt)      // 2048 tokens
#define DFF (4*Dd)      // 3072
#define NQKV (3*Dd)     // 2304

// GEMM tiling
#define TM 128
#define TN 128
#define BK 32
// smem layout (bytes): Ah[128*40*2]=10240, Al=10240, Bh[32*136*2]=8704, Bl=8704
#define SA_STRIDE 40     // bf16 elems per A row (80B, 16B-aligned, ldmatrix conflict-free)
#define SB_STRIDE 136    // bf16 elems per B row (272B, 16B-aligned)
#define OFF_AH 0
#define OFF_AL 10240
#define OFF_BH 20480
#define OFF_BL 29184
#define GEMM_SMEM 37888  // also >= 128*68*4 = 34816 for epilogue staging

// ---------------- scratch (device globals; no allocations allowed) ----------
__device__ float g_x  [Mm*Dd];
__device__ float g_tmp[Mm*Dd];
__device__ float g_qkv[(size_t)Mm*NQKV];
__device__ float g_o  [Mm*Dd];
__device__ float g_h1 [Mm*DFF];
__device__ float g_s  [(size_t)Bq*Hh*Tt*Tt];

// ---------------- mma.sync helpers ------------------------------------------
__device__ __forceinline__ uint32_t s2u(const void* p) {
    uint32_t a;
    asm("{ .reg .u64 t; cvta.to.shared.u64 t, %1; cvt.u32.u64 %0, t; }" : "=r"(a) : "l"(p));
    return a;
}
__device__ __forceinline__ void ldmx4(uint32_t* r, uint32_t addr) {
    asm volatile("ldmatrix.sync.aligned.m8n8.x4.shared.b16 {%0,%1,%2,%3},[%4];"
                 : "=r"(r[0]), "=r"(r[1]), "=r"(r[2]), "=r"(r[3]) : "r"(addr));
}
__device__ __forceinline__ void ldmx4t(uint32_t* r, uint32_t addr) {
    asm volatile("ldmatrix.sync.aligned.m8n8.x4.trans.shared.b16 {%0,%1,%2,%3},[%4];"
                 : "=r"(r[0]), "=r"(r[1]), "=r"(r[2]), "=r"(r[3]) : "r"(addr));
}
__device__ __forceinline__ void mma_bf16(float* c, const uint32_t* a,
                                         uint32_t b0, uint32_t b1) {
    asm volatile(
        "mma.sync.aligned.m16n8k16.row.col.f32.bf16.bf16.f32 "
        "{%0,%1,%2,%3},{%4,%5,%6,%7},{%8,%9},{%0,%1,%2,%3};"
        : "+f"(c[0]), "+f"(c[1]), "+f"(c[2]), "+f"(c[3])
        : "r"(a[0]), "r"(a[1]), "r"(a[2]), "r"(a[3]), "r"(b0), "r"(b1));
}
// split fp32 value pair -> packed hi bf16x2 and lo bf16x2
__device__ __forceinline__ void split_pack(float x, float y,
                                           uint32_t& hi, uint32_t& lo) {
    __nv_bfloat16 hx = __float2bfloat16_rn(x);
    __nv_bfloat16 hy = __float2bfloat16_rn(y);
    float rx = x - __bfloat162float(hx);
    float ry = y - __bfloat162float(hy);
    __nv_bfloat16 lx = __float2bfloat16_rn(rx);
    __nv_bfloat16 ly = __float2bfloat16_rn(ry);
    hi = ((uint32_t)__bfloat16_as_ushort(hy) << 16) | __bfloat16_as_ushort(hx);
    lo = ((uint32_t)__bfloat16_as_ushort(ly) << 16) | __bfloat16_as_ushort(lx);
}

// ---------------- bf16x3 tensor-core GEMM ------------------------------------
// C[M,N] = A[M,K] @ W[K,N] (+bias)(+relu), fp32 in/out.
// mode 0: W0 is [K,N] row-major. mode 1: fused QKV weight gather.
__global__ __launch_bounds__(256, 2) void gemm_bf16x3(
    const float* __restrict__ A, int lda,
    const float* __restrict__ W0, const float* __restrict__ W1,
    const float* __restrict__ W2, const float* __restrict__ bias,
    float* __restrict__ C, int ldc, int N, int K,
    int mode, int relu, int layer)
{
    extern __shared__ char smem[];
    const uint32_t sb = s2u(smem);
    const int tid = threadIdx.x;
    const int wid = tid >> 5, lane = tid & 31;
    const int m0 = blockIdx.x * TM;
    const int n0 = blockIdx.y * TN;
    const int mw = (wid & 3) * 32;     // warp m offset
    const int nw = (wid >> 2) * 64;    // warp n offset
    const int n4 = ((N & 3) == 0);

    float acc[2][8][4];
    #pragma unroll
    for (int a = 0; a < 2; a++)
        #pragma unroll
        for (int b = 0; b < 8; b++)
            #pragma unroll
            for (int c = 0; c < 4; c++) acc[a][b][c] = 0.f;

    for (int kc = 0; kc < K; kc += BK) {
        // ---- stage A [128 m][32 k]: float4 loads, hi/lo bf16 split ----
        #pragma unroll
        for (int i = 0; i < 4; i++) {
            int c = tid + i * 256;               // 1024 float4 slots
            int m = c >> 3, kq = c & 7;
            float4 v = *(const float4*)(A + (size_t)(m0 + m) * lda + kc + kq * 4);
            uint32_t h01, l01, h23, l23;
            split_pack(v.x, v.y, h01, l01);
            split_pack(v.z, v.w, h23, l23);
            uint32_t off = (uint32_t)m * (SA_STRIDE * 2) + kq * 8;
            *(uint32_t*)(smem + OFF_AH + off)     = h01;
            *(uint32_t*)(smem + OFF_AH + off + 4) = h23;
            *(uint32_t*)(smem + OFF_AL + off)     = l01;
            *(uint32_t*)(smem + OFF_AL + off + 4) = l23;
        }
        // ---- stage B [32 k][128 n] (same layout as gmem) ----
        #pragma unroll
        for (int i = 0; i < 4; i++) {
            int c = tid + i * 256;
            int k = c >> 5, nq = c & 31;
            int ng = n0 + nq * 4;
            float4 v;
            if (mode == 1) {
                int wsel = ng / Dd;
                int r2 = ng - wsel * Dd;
                int hh = r2 >> 6, s = r2 & 63;
                const float* base = (wsel == 0) ? W0 : ((wsel == 1) ? W1 : W2);
                v = *(const float4*)(base + ((size_t)(layer * Hh + hh) * Dd + (kc + k)) * HS + s);
            } else {
                const float* wr = W0 + (size_t)(kc + k) * N + ng;
                if (n4) v = *(const float4*)wr;
                else {
                    v.x = (ng     < N) ? wr[0] : 0.f;
                    v.y = (ng + 1 < N) ? wr[1] : 0.f;
                    v.z = (ng + 2 < N) ? wr[2] : 0.f;
                    v.w = (ng + 3 < N) ? wr[3] : 0.f;
                }
            }
            uint32_t h01, l01, h23, l23;
            split_pack(v.x, v.y, h01, l01);
            split_pack(v.z, v.w, h23, l23);
            uint32_t off = (uint32_t)k * (SB_STRIDE * 2) + nq * 8;
            *(uint32_t*)(smem + OFF_BH + off)     = h01;
            *(uint32_t*)(smem + OFF_BH + off + 4) = h23;
            *(uint32_t*)(smem + OFF_BL + off)     = l01;
            *(uint32_t*)(smem + OFF_BL + off + 4) = l23;
        }
        __syncthreads();

        // ---- compute: 2 k-steps of 16 ----
        #pragma unroll
        for (int kk = 0; kk < BK; kk += 16) {
            uint32_t ah[2][4], al[2][4];
            int arow = mw + (lane & 15);
            int acol = kk + (lane >> 4) * 8;
            #pragma unroll
            for (int mi = 0; mi < 2; mi++) {
                uint32_t off = (uint32_t)(arow + mi * 16) * (SA_STRIDE * 2) + acol * 2;
                ldmx4(ah[mi], sb + OFF_AH + off);
                ldmx4(al[mi], sb + OFF_AL + off);
            }
            int brow = kk + (lane & 15);
            int bcol = nw + (lane >> 4) * 8;
            #pragma unroll
            for (int ni = 0; ni < 4; ni++) {
                uint32_t off = (uint32_t)brow * (SB_STRIDE * 2) + (bcol + ni * 16) * 2;
                uint32_t bh[4], bl[4];
                ldmx4t(bh, sb + OFF_BH + off);
                ldmx4t(bl, sb + OFF_BL + off);
                #pragma unroll
                for (int mi = 0; mi < 2; mi++) {
                    mma_bf16(acc[mi][2 * ni],     ah[mi], bh[0], bh[1]);
                    mma_bf16(acc[mi][2 * ni],     ah[mi], bl[0], bl[1]);
                    mma_bf16(acc[mi][2 * ni],     al[mi], bh[0], bh[1]);
                    mma_bf16(acc[mi][2 * ni + 1], ah[mi], bh[2], bh[3]);
                    mma_bf16(acc[mi][2 * ni + 1], ah[mi], bl[2], bl[3]);
                    mma_bf16(acc[mi][2 * ni + 1], al[mi], bh[2], bh[3]);
                }
            }
        }
        __syncthreads();
    }

    // ---- epilogue: regs -> smem -> coalesced gmem, by n-half ----
    float* sC = (float*)smem;
    const int r0 = mw + (lane >> 2);
    const int c0 = 2 * (lane & 3);
    #pragma unroll 1
    for (int hf = 0; hf < 2; hf++) {
        if ((wid >> 2) == hf) {
            #pragma unroll
            for (int mi = 0; mi < 2; mi++)
                #pragma unroll
                for (int ni = 0; ni < 8; ni++) {
                    int rr = (r0 + mi * 16) * 68 + ni * 8 + c0;
                    sC[rr]           = acc[mi][ni][0];
                    sC[rr + 1]       = acc[mi][ni][1];
                    sC[rr + 8 * 68]     = acc[mi][ni][2];
                    sC[rr + 8 * 68 + 1] = acc[mi][ni][3];
                }
        }
        __syncthreads();
        #pragma unroll 4
        for (int it = 0; it < 32; it++) {
            int idx = tid + it * 256;            // 8192 = 128 x 64
            int r = idx >> 6, c = idx & 63;
            int col = n0 + hf * 64 + c;
            if (col < N) {
                float v = sC[r * 68 + c];
                if (bias) v += bias[col];
                if (relu) v = fmaxf(v, 0.f);
                C[(size_t)(m0 + r) * ldc + col] = v;
            }
        }
        __syncthreads();
    }
}

// ---------------- reductions -------------------------------------------------
__device__ __forceinline__ float block_reduce_sum(float v, float* sh) {
    int tid = threadIdx.x;
    #pragma unroll
    for (int o = 16; o > 0; o >>= 1) v += __shfl_xor_sync(0xffffffffu, v, o);
    if ((tid & 31) == 0) sh[tid >> 5] = v;
    __syncthreads();
    if (tid < 32) {
        float x = (tid < (int)(blockDim.x >> 5)) ? sh[tid] : 0.f;
        #pragma unroll
        for (int o = 4; o > 0; o >>= 1) x += __shfl_xor_sync(0xffffffffu, x, o);
        if (tid == 0) sh[0] = x;
    }
    __syncthreads();
    float r = sh[0];
    __syncthreads();
    return r;
}
__device__ __forceinline__ float block_reduce_max(float v, float* sh) {
    int tid = threadIdx.x;
    #pragma unroll
    for (int o = 16; o > 0; o >>= 1) v = fmaxf(v, __shfl_xor_sync(0xffffffffu, v, o));
    if ((tid & 31) == 0) sh[tid >> 5] = v;
    __syncthreads();
    if (tid < 32) {
        float x = (tid < (int)(blockDim.x >> 5)) ? sh[tid] : -1e30f;
        #pragma unroll
        for (int o = 4; o > 0; o >>= 1) x = fmaxf(x, __shfl_xor_sync(0xffffffffu, x, o));
        if (tid == 0) sh[0] = x;
    }
    __syncthreads();
    float r = sh[0];
    __syncthreads();
    return r;
}

// ---------------- embedding -------------------------------------------------
__global__ void embed_kernel(const int* __restrict__ idx,
                             const float* __restrict__ tok_emb,
                             const float* __restrict__ pos_emb) {
    int m = blockIdx.x;
    int t = m % Tt;
    int tok = idx[m];
    const float* te = tok_emb + (size_t)tok * Dd;
    const float* pe = pos_emb + (size_t)t * Dd;
    float* x = g_x + (size_t)m * Dd;
    for (int c = threadIdx.x; c < Dd; c += blockDim.x)
        x[c] = te[c] + pe[c];
}

// ---------------- scores: S[bh,t,u] = 0.125*dot(q[t],k[u]) ------------------
__global__ void scores_kernel() {
    int u0 = blockIdx.x * 64;
    int t0 = blockIdx.y * 64;
    if (u0 > t0 + 63) return;
    int bh = blockIdx.z;
    int b = bh / Hh, h = bh % Hh;
    const float* qb = g_qkv + (size_t)b * Tt * NQKV + h * HS;
    const float* kb = g_qkv + (size_t)b * Tt * NQKV + Dd + h * HS;
    float* Sb = g_s + (size_t)bh * Tt * Tt;

    __shared__ float Qs[16][64];
    __shared__ float Ks[16][64];
    int tid = threadIdx.x;
    int tx = tid & 15, ty = tid >> 4;
    float acc[4][4];
    #pragma unroll
    for (int i = 0; i < 4; i++)
        #pragma unroll
        for (int j = 0; j < 4; j++) acc[i][j] = 0.f;

    int rl = tid >> 2, sc = (tid & 3) * 4;

    for (int s0 = 0; s0 < HS; s0 += 16) {
        float4 qv = *(const float4*)(qb + (size_t)(t0 + rl) * NQKV + s0 + sc);
        Qs[sc + 0][rl] = qv.x; Qs[sc + 1][rl] = qv.y;
        Qs[sc + 2][rl] = qv.z; Qs[sc + 3][rl] = qv.w;
        float4 kv = *(const float4*)(kb + (size_t)(u0 + rl) * NQKV + s0 + sc);
        Ks[sc + 0][rl] = kv.x; Ks[sc + 1][rl] = kv.y;
        Ks[sc + 2][rl] = kv.z; Ks[sc + 3][rl] = kv.w;
        __syncthreads();
        #pragma unroll
        for (int kk = 0; kk < 16; kk++) {
            float a[4], bb[4];
            #pragma unroll
            for (int i = 0; i < 4; i++) a[i] = Qs[kk][ty * 4 + i];
            #pragma unroll
            for (int j = 0; j < 4; j++) bb[j] = Ks[kk][tx * 4 + j];
            #pragma unroll
            for (int i = 0; i < 4; i++)
                #pragma unroll
                for (int j = 0; j < 4; j++) acc[i][j] += a[i] * bb[j];
        }
        __syncthreads();
    }
    #pragma unroll
    for (int i = 0; i < 4; i++) {
        int t = t0 + ty * 4 + i;
        #pragma unroll
        for (int j = 0; j < 4; j++) {
            int u = u0 + tx * 4 + j;
            Sb[(size_t)t * Tt + u] = acc[i][j] * 0.125f;
        }
    }
}

// ---------------- row softmax with causal mask ------------------------------
__global__ void softmax_kernel() {
    __shared__ float sh[8];
    int row = blockIdx.x;
    int t = row % Tt;
    float* p = g_s + (size_t)row * Tt;
    int n = t + 1;
    int tid = threadIdx.x;

    float m = -1e30f;
    for (int u = tid; u < n; u += 256) m = fmaxf(m, p[u]);
    m = block_reduce_max(m, sh);

    float s = 0.f;
    for (int u = tid; u < n; u += 256) {
        float e = __expf(p[u] - m);
        p[u] = e;
        s += e;
    }
    s = block_reduce_sum(s, sh);
    float inv = 1.f / s;
    for (int u = tid; u < n; u += 256) p[u] *= inv;
    for (int u = n + tid; u < Tt; u += 256) p[u] = 0.f;
}

// ---------------- PV: O[b,t,h*HS+s] = sum_u P[t,u]*v[u,s] -------------------
__global__ void pv_kernel() {
    int bh = blockIdx.z;
    int t0 = blockIdx.y * 64;
    const float* Pb = g_s + (size_t)bh * Tt * Tt;
    int b = bh / Hh, h = bh % Hh;
    const float* vb = g_qkv + (size_t)b * Tt * NQKV + 2 * Dd + h * HS;

    __shared__ float Ps[16][64];
    __shared__ float Vs[16][64];
    int tid = threadIdx.x;
    int tx = tid & 15, ty = tid >> 4;
    float acc[4][4];
    #pragma unroll
    for (int i = 0; i < 4; i++)
        #pragma unroll
        for (int j = 0; j < 4; j++) acc[i][j] = 0.f;

    int tl = tid >> 2, uk = (tid & 3) * 4;
    int bu = tid >> 4, sn = (tid & 15) * 4;

    for (int u0 = 0; u0 < t0 + 64; u0 += 16) {
        float4 pv = *(const float4*)(Pb + (size_t)(t0 + tl) * Tt + u0 + uk);
        Ps[uk + 0][tl] = pv.x; Ps[uk + 1][tl] = pv.y;
        Ps[uk + 2][tl] = pv.z; Ps[uk + 3][tl] = pv.w;
        float4 vv = *(const float4*)(vb + (size_t)(u0 + bu) * NQKV + sn);
        Vs[bu][sn + 0] = vv.x; Vs[bu][sn + 1] = vv.y;
        Vs[bu][sn + 2] = vv.z; Vs[bu][sn + 3] = vv.w;
        __syncthreads();
        #pragma unroll
        for (int kk = 0; kk < 16; kk++) {
            float a[4], b2[4];
            #pragma unroll
            for (int i = 0; i < 4; i++) a[i] = Ps[kk][ty * 4 + i];
            #pragma unroll
            for (int j = 0; j < 4; j++) b2[j] = Vs[kk][tx * 4 + j];
            #pragma unroll
            for (int i = 0; i < 4; i++)
                #pragma unroll
                for (int j = 0; j < 4; j++) acc[i][j] += a[i] * b2[j];
        }
        __syncthreads();
    }
    #pragma unroll
    for (int i = 0; i < 4; i++) {
        int t = t0 + ty * 4 + i;
        float* orow = g_o + ((size_t)(b * Tt + t) * Dd + h * HS);
        #pragma unroll
        for (int j = 0; j < 4; j++) orow[tx * 4 + j] = acc[i][j];
    }
}

// ---------------- fused residual add + LayerNorm ----------------------------
__global__ void addln_kernel(const float* __restrict__ add,
                             const float* __restrict__ gamma,
                             const float* __restrict__ beta) {
    __shared__ float sh[8];
    int m = blockIdx.x;
    float* x = g_x + (size_t)m * Dd;
    const float* a = add + (size_t)m * Dd;
    int tid = threadIdx.x;

    float v[3];
    float s = 0.f;
    #pragma unroll
    for (int i = 0; i < 3; i++) {
        int c = tid + i * 256;
        v[i] = x[c] + a[c];
        s += v[i];
    }
    s = block_reduce_sum(s, sh);
    float mean = s * (1.f / Dd);

    float q = 0.f;
    #pragma unroll
    for (int i = 0; i < 3; i++) {
        float d = v[i] - mean;
        q += d * d;
    }
    q = block_reduce_sum(q, sh);
    float rstd = rsqrtf(q * (1.f / Dd) + 1e-5f);

    #pragma unroll
    for (int i = 0; i < 3; i++) {
        int c = tid + i * 256;
        x[c] = (v[i] - mean) * rstd * gamma[c] + beta[c];
    }
}

// ---------------- host orchestration ----------------------------------------
extern "C" void kernel_launch(void* const* d_in, const int* in_sizes, int n_in,
                              void* d_out, int out_size) {
    const int*   idx     = (const int*)  d_in[0];
    const float* tok_emb = (const float*)d_in[1];
    const float* pos_emb = (const float*)d_in[2];
    const float* wq      = (const float*)d_in[3];
    const float* wk      = (const float*)d_in[4];
    const float* wv      = (const float*)d_in[5];
    const float* wproj   = (const float*)d_in[6];
    const float* bproj   = (const float*)d_in[7];
    const float* w1      = (const float*)d_in[8];
    const float* b1      = (const float*)d_in[9];
    const float* w2      = (const float*)d_in[10];
    const float* b2      = (const float*)d_in[11];
    const float* ln1_g   = (const float*)d_in[12];
    const float* ln1_b   = (const float*)d_in[13];
    const float* ln2_g   = (const float*)d_in[14];
    const float* ln2_b   = (const float*)d_in[15];
    const float* lm_w    = (const float*)d_in[16];
    const float* lm_b    = (const float*)d_in[17];
    float* out = (float*)d_out;

    float *p_x, *p_tmp, *p_o, *p_h1, *p_qkv;
    cudaGetSymbolAddress((void**)&p_x,   g_x);
    cudaGetSymbolAddress((void**)&p_tmp, g_tmp);
    cudaGetSymbolAddress((void**)&p_o,   g_o);
    cudaGetSymbolAddress((void**)&p_h1,  g_h1);
    cudaGetSymbolAddress((void**)&p_qkv, g_qkv);

    embed_kernel<<<Mm, 256>>>(idx, tok_emb, pos_emb);

    for (int l = 0; l < Ll; l++) {
        gemm_bf16x3<<<dim3(Mm / TM, NQKV / TN), 256, GEMM_SMEM>>>(
            p_x, Dd, wq, wk, wv, nullptr, p_qkv, NQKV, NQKV, Dd, 1, 0, l);
        scores_kernel <<<dim3(Tt / 64, Tt / 64, Bq * Hh), 256>>>();
        softmax_kernel<<<Bq * Hh * Tt, 256>>>();
        pv_kernel     <<<dim3(1, Tt / 64, Bq * Hh), 256>>>();
        gemm_bf16x3<<<dim3(Mm / TM, Dd / TN), 256, GEMM_SMEM>>>(
            p_o, Dd, wproj + (size_t)l * Dd * Dd, nullptr, nullptr,
            bproj + (size_t)l * Dd, p_tmp, Dd, Dd, Dd, 0, 0, 0);
        addln_kernel<<<Mm, 256>>>(p_tmp, ln1_g + (size_t)l * Dd, ln1_b + (size_t)l * Dd);
        gemm_bf16x3<<<dim3(Mm / TM, DFF / TN), 256, GEMM_SMEM>>>(
            p_x, Dd, w1 + (size_t)l * Dd * DFF, nullptr, nullptr,
            b1 + (size_t)l * DFF, p_h1, DFF, DFF, Dd, 0, 1, 0);
        gemm_bf16x3<<<dim3(Mm / TM, Dd / TN), 256, GEMM_SMEM>>>(
            p_h1, DFF, w2 + (size_t)l * DFF * Dd, nullptr, nullptr,
            b2 + (size_t)l * Dd, p_tmp, Dd, Dd, DFF, 0, 0, 0);
        addln_kernel<<<Mm, 256>>>(p_tmp, ln2_g + (size_t)l * Dd, ln2_b + (size_t)l * Dd);
    }

    gemm_bf16x3<<<dim3(Mm / TM, (Vv + TN - 1) / TN), 256, GEMM_SMEM>>>(
        p_x, Dd, lm_w, nullptr, nullptr, lm_b, out, Vv, Vv, Dd, 0, 0, 0);
}

// round 4
// speedup vs baseline: 3.0598x; 1.2341x over previous
#include <cuda_runtime.h>
#include <cuda_bf16.h>
#include <cstdint>
#include <math.h>
#include <stddef.h>

// Problem constants
#define Bq 2
#define Tt 1024
#define Dd 768
#define Hh 12
#define Ll 6
#define Vv 50257
#define VP 50304          // Vv padded to multiple of 128
#define HS 64
#define Mm (Bq*Tt)        // 2048
#define DFF (4*Dd)        // 3072
#define NQKV (3*Dd)       // 2304

// GEMM tiling
#define TM 128
#define TN 128
#define BK 32
#define SA_STRIDE 40      // bf16 elems per A smem row (80B)
#define SB_STRIDE 136     // bf16 elems per B smem row (272B)
#define OFF_AH 0
#define OFF_AL 10240
#define OFF_BH 20480
#define OFF_BL 29184
#define STAGE_BYTES 37888
#define GEMM_SMEM (2*STAGE_BYTES)   // 75776

// ---------------- scratch (device globals) -----------------------------------
__device__ float g_x  [Mm*Dd];
__device__ float g_tmp[Mm*Dd];
__device__ float g_qkv[(size_t)Mm*NQKV];
__device__ float g_s  [(size_t)Bq*Hh*Tt*Tt];

__device__ __nv_bfloat16 x_h [Mm*Dd],  x_l [Mm*Dd];
__device__ __nv_bfloat16 o_h [Mm*Dd],  o_l [Mm*Dd];
__device__ __nv_bfloat16 h1_h[(size_t)Mm*DFF], h1_l[(size_t)Mm*DFF];

__device__ __nv_bfloat16 wqkv_h[(size_t)Ll*Dd*NQKV], wqkv_l[(size_t)Ll*Dd*NQKV];
__device__ __nv_bfloat16 wpr_h [(size_t)Ll*Dd*Dd],   wpr_l [(size_t)Ll*Dd*Dd];
__device__ __nv_bfloat16 w1b_h [(size_t)Ll*Dd*DFF],  w1b_l [(size_t)Ll*Dd*DFF];
__device__ __nv_bfloat16 w2b_h [(size_t)Ll*DFF*Dd],  w2b_l [(size_t)Ll*DFF*Dd];
__device__ __nv_bfloat16 lmw_h [(size_t)Dd*VP],      lmw_l [(size_t)Dd*VP];

// ---------------- helpers -----------------------------------------------------
__device__ __forceinline__ uint32_t s2u(const void* p) {
    uint32_t a;
    asm("{ .reg .u64 t; cvta.to.shared.u64 t, %1; cvt.u32.u64 %0, t; }" : "=r"(a) : "l"(p));
    return a;
}
__device__ __forceinline__ void cpa16(uint32_t dst, const void* src) {
    asm volatile("cp.async.cg.shared.global [%0], [%1], 16;" :: "r"(dst), "l"(src));
}
__device__ __forceinline__ void ldmx4(uint32_t* r, uint32_t addr) {
    asm volatile("ldmatrix.sync.aligned.m8n8.x4.shared.b16 {%0,%1,%2,%3},[%4];"
                 : "=r"(r[0]), "=r"(r[1]), "=r"(r[2]), "=r"(r[3]) : "r"(addr));
}
__device__ __forceinline__ void ldmx4t(uint32_t* r, uint32_t addr) {
    asm volatile("ldmatrix.sync.aligned.m8n8.x4.trans.shared.b16 {%0,%1,%2,%3},[%4];"
                 : "=r"(r[0]), "=r"(r[1]), "=r"(r[2]), "=r"(r[3]) : "r"(addr));
}
__device__ __forceinline__ void mma_bf16(float* c, const uint32_t* a,
                                         uint32_t b0, uint32_t b1) {
    asm volatile(
        "mma.sync.aligned.m16n8k16.row.col.f32.bf16.bf16.f32 "
        "{%0,%1,%2,%3},{%4,%5,%6,%7},{%8,%9},{%0,%1,%2,%3};"
        : "+f"(c[0]), "+f"(c[1]), "+f"(c[2]), "+f"(c[3])
        : "r"(a[0]), "r"(a[1]), "r"(a[2]), "r"(a[3]), "r"(b0), "r"(b1));
}
__device__ __forceinline__ void splitv(float v, __nv_bfloat16& h, __nv_bfloat16& l) {
    h = __float2bfloat16_rn(v);
    l = __float2bfloat16_rn(v - __bfloat162float(h));
}

// ---------------- weight conversion kernels ----------------------------------
__global__ void split_flat(const float* __restrict__ src,
                           __nv_bfloat16* __restrict__ h,
                           __nv_bfloat16* __restrict__ l, size_t n) {
    for (size_t i = (size_t)blockIdx.x * blockDim.x + threadIdx.x; i < n;
         i += (size_t)gridDim.x * blockDim.x) {
        splitv(src[i], h[i], l[i]);
    }
}
// build fused QKV weight [L][K=768][N=2304]
__global__ void conv_qkv(const float* __restrict__ wq,
                         const float* __restrict__ wk,
                         const float* __restrict__ wv) {
    const size_t total = (size_t)Ll * Dd * NQKV;
    for (size_t i = (size_t)blockIdx.x * blockDim.x + threadIdx.x; i < total;
         i += (size_t)gridDim.x * blockDim.x) {
        size_t l = i / ((size_t)Dd * NQKV);
        size_t r = i - l * ((size_t)Dd * NQKV);
        int k = (int)(r / NQKV);
        int n = (int)(r - (size_t)k * NQKV);
        int wsel = n / Dd;
        int r2 = n - wsel * Dd;
        int hh = r2 >> 6, s = r2 & 63;
        const float* base = (wsel == 0) ? wq : ((wsel == 1) ? wk : wv);
        float v = base[(((size_t)l * Hh + hh) * Dd + k) * HS + s];
        splitv(v, wqkv_h[i], wqkv_l[i]);
    }
}
__global__ void conv_lm(const float* __restrict__ lm_w) {
    const size_t total = (size_t)Dd * VP;
    for (size_t i = (size_t)blockIdx.x * blockDim.x + threadIdx.x; i < total;
         i += (size_t)gridDim.x * blockDim.x) {
        int k = (int)(i / VP);
        int n = (int)(i - (size_t)k * VP);
        float v = (n < Vv) ? lm_w[(size_t)k * Vv + n] : 0.f;
        splitv(v, lmw_h[i], lmw_l[i]);
    }
}

// ---------------- bf16x3 tensor-core GEMM (cp.async double-buffered) ---------
// C = A(M x K) @ B(K x N'), A/B pre-split bf16 hi/lo. ldb = padded N.
// outmode 0: fp32 C (+bias,+relu), store guarded col < N.
// outmode 1: bf16 hi/lo pair Ch/Cl (+bias,+relu).
__global__ __launch_bounds__(256, 2) void gemm_bf3(
    const __nv_bfloat16* __restrict__ Ah_g, const __nv_bfloat16* __restrict__ Al_g,
    int lda,
    const __nv_bfloat16* __restrict__ Bh_g, const __nv_bfloat16* __restrict__ Bl_g,
    int ldb,
    const float* __restrict__ bias,
    float* __restrict__ Cf,
    __nv_bfloat16* __restrict__ Ch, __nv_bfloat16* __restrict__ Cl,
    int ldc, int N, int K, int relu, int outmode)
{
    extern __shared__ char smem[];
    const uint32_t sb = s2u(smem);
    const int tid = threadIdx.x;
    const int wid = tid >> 5, lane = tid & 31;
    const int m0 = blockIdx.x * TM;
    const int n0 = blockIdx.y * TN;
    const int mw = (wid & 3) * 32;
    const int nw = (wid >> 2) * 64;

    float acc[2][8][4];
    #pragma unroll
    for (int a = 0; a < 2; a++)
        #pragma unroll
        for (int b = 0; b < 8; b++)
            #pragma unroll
            for (int c = 0; c < 4; c++) acc[a][b][c] = 0.f;

    auto load_stage = [&](int kc, int st) {
        uint32_t base = sb + st * STAGE_BYTES;
        // A hi/lo: 512 chunks each (128 rows x 4 chunks)
        #pragma unroll
        for (int i = 0; i < 2; i++) {
            int c = tid + i * 256;
            int row = c >> 2, q = c & 3;
            uint32_t d = base + OFF_AH + row * 80 + q * 16;
            cpa16(d, Ah_g + (size_t)(m0 + row) * lda + kc + q * 8);
            cpa16(d + (OFF_AL - OFF_AH), Al_g + (size_t)(m0 + row) * lda + kc + q * 8);
        }
        // B hi/lo: 512 chunks each (32 rows x 16 chunks)
        #pragma unroll
        for (int i = 0; i < 2; i++) {
            int c = tid + i * 256;
            int row = c >> 4, q = c & 15;
            uint32_t d = base + OFF_BH + row * 272 + q * 16;
            cpa16(d, Bh_g + (size_t)(kc + row) * ldb + n0 + q * 8);
            cpa16(d + (OFF_BL - OFF_BH), Bl_g + (size_t)(kc + row) * ldb + n0 + q * 8);
        }
        asm volatile("cp.async.commit_group;" ::: "memory");
    };

    const int niter = K / BK;
    load_stage(0, 0);

    for (int it = 0; it < niter; it++) {
        if (it + 1 < niter) {
            load_stage((it + 1) * BK, (it + 1) & 1);
            asm volatile("cp.async.wait_group 1;" ::: "memory");
        } else {
            asm volatile("cp.async.wait_group 0;" ::: "memory");
        }
        __syncthreads();

        const uint32_t sbase = sb + (it & 1) * STAGE_BYTES;
        #pragma unroll
        for (int kk = 0; kk < BK; kk += 16) {
            uint32_t ah[2][4], al[2][4];
            int arow = mw + (lane & 15);
            int acol = kk + (lane >> 4) * 8;
            #pragma unroll
            for (int mi = 0; mi < 2; mi++) {
                uint32_t off = (uint32_t)(arow + mi * 16) * (SA_STRIDE * 2) + acol * 2;
                ldmx4(ah[mi], sbase + OFF_AH + off);
                ldmx4(al[mi], sbase + OFF_AL + off);
            }
            int brow = kk + (lane & 15);
            int bcol = nw + (lane >> 4) * 8;
            #pragma unroll
            for (int ni = 0; ni < 4; ni++) {
                uint32_t off = (uint32_t)brow * (SB_STRIDE * 2) + (bcol + ni * 16) * 2;
                uint32_t bh[4], bl[4];
                ldmx4t(bh, sbase + OFF_BH + off);
                ldmx4t(bl, sbase + OFF_BL + off);
                #pragma unroll
                for (int mi = 0; mi < 2; mi++) {
                    mma_bf16(acc[mi][2 * ni],     ah[mi], bh[0], bh[1]);
                    mma_bf16(acc[mi][2 * ni],     ah[mi], bl[0], bl[1]);
                    mma_bf16(acc[mi][2 * ni],     al[mi], bh[0], bh[1]);
                    mma_bf16(acc[mi][2 * ni + 1], ah[mi], bh[2], bh[3]);
                    mma_bf16(acc[mi][2 * ni + 1], ah[mi], bl[2], bl[3]);
                    mma_bf16(acc[mi][2 * ni + 1], al[mi], bh[2], bh[3]);
                }
            }
        }
        __syncthreads();
    }

    // ---- epilogue: regs -> smem -> coalesced gmem, by n-half ----
    float* sC = (float*)smem;
    const int r0 = mw + (lane >> 2);
    const int c0 = 2 * (lane & 3);
    #pragma unroll 1
    for (int hf = 0; hf < 2; hf++) {
        if ((wid >> 2) == hf) {
            #pragma unroll
            for (int mi = 0; mi < 2; mi++)
                #pragma unroll
                for (int ni = 0; ni < 8; ni++) {
                    int rr = (r0 + mi * 16) * 68 + ni * 8 + c0;
                    sC[rr]              = acc[mi][ni][0];
                    sC[rr + 1]          = acc[mi][ni][1];
                    sC[rr + 8 * 68]     = acc[mi][ni][2];
                    sC[rr + 8 * 68 + 1] = acc[mi][ni][3];
                }
        }
        __syncthreads();
        #pragma unroll 4
        for (int it = 0; it < 32; it++) {
            int idx = tid + it * 256;            // 8192 = 128 x 64
            int r = idx >> 6, c = idx & 63;
            int col = n0 + hf * 64 + c;
            if (col < N) {
                float v = sC[r * 68 + c];
                if (bias) v += bias[col];
                if (relu) v = fmaxf(v, 0.f);
                if (outmode == 0) {
                    Cf[(size_t)(m0 + r) * ldc + col] = v;
                } else {
                    __nv_bfloat16 hh, ll;
                    splitv(v, hh, ll);
                    Ch[(size_t)(m0 + r) * ldc + col] = hh;
                    Cl[(size_t)(m0 + r) * ldc + col] = ll;
                }
            }
        }
        __syncthreads();
    }
}

// ---------------- reductions --------------------------------------------------
__device__ __forceinline__ float block_reduce_sum(float v, float* sh) {
    int tid = threadIdx.x;
    #pragma unroll
    for (int o = 16; o > 0; o >>= 1) v += __shfl_xor_sync(0xffffffffu, v, o);
    if ((tid & 31) == 0) sh[tid >> 5] = v;
    __syncthreads();
    if (tid < 32) {
        float x = (tid < (int)(blockDim.x >> 5)) ? sh[tid] : 0.f;
        #pragma unroll
        for (int o = 4; o > 0; o >>= 1) x += __shfl_xor_sync(0xffffffffu, x, o);
        if (tid == 0) sh[0] = x;
    }
    __syncthreads();
    float r = sh[0];
    __syncthreads();
    return r;
}
__device__ __forceinline__ float block_reduce_max(float v, float* sh) {
    int tid = threadIdx.x;
    #pragma unroll
    for (int o = 16; o > 0; o >>= 1) v = fmaxf(v, __shfl_xor_sync(0xffffffffu, v, o));
    if ((tid & 31) == 0) sh[tid >> 5] = v;
    __syncthreads();
    if (tid < 32) {
        float x = (tid < (int)(blockDim.x >> 5)) ? sh[tid] : -1e30f;
        #pragma unroll
        for (int o = 4; o > 0; o >>= 1) x = fmaxf(x, __shfl_xor_sync(0xffffffffu, x, o));
        if (tid == 0) sh[0] = x;
    }
    __syncthreads();
    float r = sh[0];
    __syncthreads();
    return r;
}

// ---------------- embedding ---------------------------------------------------
__global__ void embed_kernel(const int* __restrict__ idx,
                             const float* __restrict__ tok_emb,
                             const float* __restrict__ pos_emb) {
    int m = blockIdx.x;
    int t = m % Tt;
    int tok = idx[m];
    const float* te = tok_emb + (size_t)tok * Dd;
    const float* pe = pos_emb + (size_t)t * Dd;
    float* x = g_x + (size_t)m * Dd;
    for (int c = threadIdx.x; c < Dd; c += blockDim.x) {
        float v = te[c] + pe[c];
        x[c] = v;
        splitv(v, x_h[(size_t)m * Dd + c], x_l[(size_t)m * Dd + c]);
    }
}

// ---------------- scores ------------------------------------------------------
__global__ void scores_kernel() {
    int u0 = blockIdx.x * 64;
    int t0 = blockIdx.y * 64;
    if (u0 > t0 + 63) return;
    int bh = blockIdx.z;
    int b = bh / Hh, h = bh % Hh;
    const float* qb = g_qkv + (size_t)b * Tt * NQKV + h * HS;
    const float* kb = g_qkv + (size_t)b * Tt * NQKV + Dd + h * HS;
    float* Sb = g_s + (size_t)bh * Tt * Tt;

    __shared__ float Qs[16][64];
    __shared__ float Ks[16][64];
    int tid = threadIdx.x;
    int tx = tid & 15, ty = tid >> 4;
    float acc[4][4];
    #pragma unroll
    for (int i = 0; i < 4; i++)
        #pragma unroll
        for (int j = 0; j < 4; j++) acc[i][j] = 0.f;

    int rl = tid >> 2, sc = (tid & 3) * 4;

    for (int s0 = 0; s0 < HS; s0 += 16) {
        float4 qv = *(const float4*)(qb + (size_t)(t0 + rl) * NQKV + s0 + sc);
        Qs[sc + 0][rl] = qv.x; Qs[sc + 1][rl] = qv.y;
        Qs[sc + 2][rl] = qv.z; Qs[sc + 3][rl] = qv.w;
        float4 kv = *(const float4*)(kb + (size_t)(u0 + rl) * NQKV + s0 + sc);
        Ks[sc + 0][rl] = kv.x; Ks[sc + 1][rl] = kv.y;
        Ks[sc + 2][rl] = kv.z; Ks[sc + 3][rl] = kv.w;
        __syncthreads();
        #pragma unroll
        for (int kk = 0; kk < 16; kk++) {
            float a[4], bb[4];
            #pragma unroll
            for (int i = 0; i < 4; i++) a[i] = Qs[kk][ty * 4 + i];
            #pragma unroll
            for (int j = 0; j < 4; j++) bb[j] = Ks[kk][tx * 4 + j];
            #pragma unroll
            for (int i = 0; i < 4; i++)
                #pragma unroll
                for (int j = 0; j < 4; j++) acc[i][j] += a[i] * bb[j];
        }
        __syncthreads();
    }
    #pragma unroll
    for (int i = 0; i < 4; i++) {
        int t = t0 + ty * 4 + i;
        #pragma unroll
        for (int j = 0; j < 4; j++) {
            int u = u0 + tx * 4 + j;
            Sb[(size_t)t * Tt + u] = acc[i][j] * 0.125f;
        }
    }
}

// ---------------- row softmax with causal mask --------------------------------
__global__ void softmax_kernel() {
    __shared__ float sh[8];
    int row = blockIdx.x;
    int t = row % Tt;
    float* p = g_s + (size_t)row * Tt;
    int n = t + 1;
    int tid = threadIdx.x;

    float m = -1e30f;
    for (int u = tid; u < n; u += 256) m = fmaxf(m, p[u]);
    m = block_reduce_max(m, sh);

    float s = 0.f;
    for (int u = tid; u < n; u += 256) {
        float e = __expf(p[u] - m);
        p[u] = e;
        s += e;
    }
    s = block_reduce_sum(s, sh);
    float inv = 1.f / s;
    for (int u = tid; u < n; u += 256) p[u] *= inv;
    for (int u = n + tid; u < Tt; u += 256) p[u] = 0.f;
}

// ---------------- PV ----------------------------------------------------------
__global__ void pv_kernel() {
    int bh = blockIdx.z;
    int t0 = blockIdx.y * 64;
    const float* Pb = g_s + (size_t)bh * Tt * Tt;
    int b = bh / Hh, h = bh % Hh;
    const float* vb = g_qkv + (size_t)b * Tt * NQKV + 2 * Dd + h * HS;

    __shared__ float Ps[16][64];
    __shared__ float Vs[16][64];
    int tid = threadIdx.x;
    int tx = tid & 15, ty = tid >> 4;
    float acc[4][4];
    #pragma unroll
    for (int i = 0; i < 4; i++)
        #pragma unroll
        for (int j = 0; j < 4; j++) acc[i][j] = 0.f;

    int tl = tid >> 2, uk = (tid & 3) * 4;
    int bu = tid >> 4, sn = (tid & 15) * 4;

    for (int u0 = 0; u0 < t0 + 64; u0 += 16) {
        float4 pv = *(const float4*)(Pb + (size_t)(t0 + tl) * Tt + u0 + uk);
        Ps[uk + 0][tl] = pv.x; Ps[uk + 1][tl] = pv.y;
        Ps[uk + 2][tl] = pv.z; Ps[uk + 3][tl] = pv.w;
        float4 vv = *(const float4*)(vb + (size_t)(u0 + bu) * NQKV + sn);
        Vs[bu][sn + 0] = vv.x; Vs[bu][sn + 1] = vv.y;
        Vs[bu][sn + 2] = vv.z; Vs[bu][sn + 3] = vv.w;
        __syncthreads();
        #pragma unroll
        for (int kk = 0; kk < 16; kk++) {
            float a[4], b2[4];
            #pragma unroll
            for (int i = 0; i < 4; i++) a[i] = Ps[kk][ty * 4 + i];
            #pragma unroll
            for (int j = 0; j < 4; j++) b2[j] = Vs[kk][tx * 4 + j];
            #pragma unroll
            for (int i = 0; i < 4; i++)
                #pragma unroll
                for (int j = 0; j < 4; j++) acc[i][j] += a[i] * b2[j];
        }
        __syncthreads();
    }
    #pragma unroll
    for (int i = 0; i < 4; i++) {
        int t = t0 + ty * 4 + i;
        size_t base = (size_t)(b * Tt + t) * Dd + h * HS + tx * 4;
        #pragma unroll
        for (int j = 0; j < 4; j++)
            splitv(acc[i][j], o_h[base + j], o_l[base + j]);
    }
}

// ---------------- fused residual add + LayerNorm (writes fp32 + bf16 pair) ---
__global__ void addln_kernel(const float* __restrict__ add,
                             const float* __restrict__ gamma,
                             const float* __restrict__ beta) {
    __shared__ float sh[8];
    int m = blockIdx.x;
    float* x = g_x + (size_t)m * Dd;
    const float* a = add + (size_t)m * Dd;
    int tid = threadIdx.x;

    float v[3];
    float s = 0.f;
    #pragma unroll
    for (int i = 0; i < 3; i++) {
        int c = tid + i * 256;
        v[i] = x[c] + a[c];
        s += v[i];
    }
    s = block_reduce_sum(s, sh);
    float mean = s * (1.f / Dd);

    float q = 0.f;
    #pragma unroll
    for (int i = 0; i < 3; i++) {
        float d = v[i] - mean;
        q += d * d;
    }
    q = block_reduce_sum(q, sh);
    float rstd = rsqrtf(q * (1.f / Dd) + 1e-5f);

    #pragma unroll
    for (int i = 0; i < 3; i++) {
        int c = tid + i * 256;
        float o = (v[i] - mean) * rstd * gamma[c] + beta[c];
        x[c] = o;
        splitv(o, x_h[(size_t)m * Dd + c], x_l[(size_t)m * Dd + c]);
    }
}

// ---------------- host orchestration ------------------------------------------
extern "C" void kernel_launch(void* const* d_in, const int* in_sizes, int n_in,
                              void* d_out, int out_size) {
    const int*   idx     = (const int*)  d_in[0];
    const float* tok_emb = (const float*)d_in[1];
    const float* pos_emb = (const float*)d_in[2];
    const float* wq      = (const float*)d_in[3];
    const float* wk      = (const float*)d_in[4];
    const float* wv      = (const float*)d_in[5];
    const float* wproj   = (const float*)d_in[6];
    const float* bproj   = (const float*)d_in[7];
    const float* w1      = (const float*)d_in[8];
    const float* b1      = (const float*)d_in[9];
    const float* w2      = (const float*)d_in[10];
    const float* b2      = (const float*)d_in[11];
    const float* ln1_g   = (const float*)d_in[12];
    const float* ln1_b   = (const float*)d_in[13];
    const float* ln2_g   = (const float*)d_in[14];
    const float* ln2_b   = (const float*)d_in[15];
    const float* lm_w    = (const float*)d_in[16];
    const float* lm_b    = (const float*)d_in[17];
    float* out = (float*)d_out;

    cudaFuncSetAttribute(gemm_bf3, cudaFuncAttributeMaxDynamicSharedMemorySize, GEMM_SMEM);

    float *p_x, *p_tmp, *p_qkv;
    cudaGetSymbolAddress((void**)&p_x,   g_x);
    cudaGetSymbolAddress((void**)&p_tmp, g_tmp);
    cudaGetSymbolAddress((void**)&p_qkv, g_qkv);
    __nv_bfloat16 *pxh, *pxl, *poh, *pol, *ph1h, *ph1l;
    cudaGetSymbolAddress((void**)&pxh, x_h);   cudaGetSymbolAddress((void**)&pxl, x_l);
    cudaGetSymbolAddress((void**)&poh, o_h);   cudaGetSymbolAddress((void**)&pol, o_l);
    cudaGetSymbolAddress((void**)&ph1h, h1_h); cudaGetSymbolAddress((void**)&ph1l, h1_l);
    __nv_bfloat16 *pwqh, *pwql, *pwph, *pwpl, *pw1h, *pw1l, *pw2h, *pw2l, *plmh, *plml;
    cudaGetSymbolAddress((void**)&pwqh, wqkv_h); cudaGetSymbolAddress((void**)&pwql, wqkv_l);
    cudaGetSymbolAddress((void**)&pwph, wpr_h);  cudaGetSymbolAddress((void**)&pwpl, wpr_l);
    cudaGetSymbolAddress((void**)&pw1h, w1b_h);  cudaGetSymbolAddress((void**)&pw1l, w1b_l);
    cudaGetSymbolAddress((void**)&pw2h, w2b_h);  cudaGetSymbolAddress((void**)&pw2l, w2b_l);
    cudaGetSymbolAddress((void**)&plmh, lmw_h);  cudaGetSymbolAddress((void**)&plml, lmw_l);

    // weight conversions (once per call)
    conv_qkv<<<2048, 256>>>(wq, wk, wv);
    split_flat<<<2048, 256>>>(wproj, pwph, pwpl, (size_t)Ll * Dd * Dd);
    split_flat<<<2048, 256>>>(w1, pw1h, pw1l, (size_t)Ll * Dd * DFF);
    split_flat<<<2048, 256>>>(w2, pw2h, pw2l, (size_t)Ll * DFF * Dd);
    conv_lm<<<4096, 256>>>(lm_w);

    embed_kernel<<<Mm, 256>>>(idx, tok_emb, pos_emb);

    for (int l = 0; l < Ll; l++) {
        // QKV: [2048,2304] fp32 out
        gemm_bf3<<<dim3(Mm / TM, NQKV / TN), 256, GEMM_SMEM>>>(
            pxh, pxl, Dd,
            pwqh + (size_t)l * Dd * NQKV, pwql + (size_t)l * Dd * NQKV, NQKV,
            nullptr, p_qkv, nullptr, nullptr, NQKV, NQKV, Dd, 0, 0);
        scores_kernel <<<dim3(Tt / 64, Tt / 64, Bq * Hh), 256>>>();
        softmax_kernel<<<Bq * Hh * Tt, 256>>>();
        pv_kernel     <<<dim3(1, Tt / 64, Bq * Hh), 256>>>();
        // proj: fp32 out to tmp
        gemm_bf3<<<dim3(Mm / TM, Dd / TN), 256, GEMM_SMEM>>>(
            poh, pol, Dd,
            pwph + (size_t)l * Dd * Dd, pwpl + (size_t)l * Dd * Dd, Dd,
            bproj + (size_t)l * Dd, p_tmp, nullptr, nullptr, Dd, Dd, Dd, 0, 0);
        addln_kernel<<<Mm, 256>>>(p_tmp, ln1_g + (size_t)l * Dd, ln1_b + (size_t)l * Dd);
        // fc1: bf16 pair out + relu
        gemm_bf3<<<dim3(Mm / TM, DFF / TN), 256, GEMM_SMEM>>>(
            pxh, pxl, Dd,
            pw1h + (size_t)l * Dd * DFF, pw1l + (size_t)l * Dd * DFF, DFF,
            b1 + (size_t)l * DFF, nullptr, ph1h, ph1l, DFF, DFF, Dd, 1, 1);
        // fc2: fp32 out to tmp
        gemm_bf3<<<dim3(Mm / TM, Dd / TN), 256, GEMM_SMEM>>>(
            ph1h, ph1l, DFF,
            pw2h + (size_t)l * DFF * Dd, pw2l + (size_t)l * DFF * Dd, Dd,
            b2 + (size_t)l * Dd, p_tmp, nullptr, nullptr, Dd, Dd, DFF, 0, 0);
        addln_kernel<<<Mm, 256>>>(p_tmp, ln2_g + (size_t)l * Dd, ln2_b + (size_t)l * Dd);
    }

    // logits: N=Vv, ldb=VP (padded), ldc=Vv
    gemm_bf3<<<dim3(Mm / TM, VP / TN), 256, GEMM_SMEM>>>(
        pxh, pxl, Dd, plmh, plml, VP,
        lm_b, out, nullptr, nullptr, Vv, Vv, Dd, 0, 0);
}

// round 5
// speedup vs baseline: 3.7856x; 1.2372x over previous
#include <cuda_runtime.h>
#include <cuda_bf16.h>
#include <cstdint>
#include <math.h>
#include <stddef.h>

// Problem constants
#define Bq 2
#define Tt 1024
#define Dd 768
#define Hh 12
#define Ll 6
#define Vv 50257
#define VP 50304
#define HS 64
#define Mm (Bq*Tt)
#define DFF (4*Dd)
#define NQKV (3*Dd)

// GEMM tiling
#define TM 128
#define TN 128
#define BK 32
#define SA_STRIDE 40
#define SB_STRIDE 136
#define OFF_AH 0
#define OFF_AL 10240
#define OFF_BH 20480
#define OFF_BL 29184
#define STAGE_BYTES 37888
#define GEMM_SMEM (2*STAGE_BYTES)

// Flash attention tiling
#define FBM 128
#define FBN 64
#define FKP 72              // bf16 stride for Q/K/V smem rows (144 B)
#define FST_KH 0
#define FST_KL 9216
#define FST_VH 18432
#define FST_VL 27648
#define FSTAGE 36864
#define FLASH_SMEM (2*FSTAGE)  // 73728; Q staging (Qh@0 18432B, Ql@18432) fits stage0

// ---------------- scratch --------------------------------------------------
__device__ float g_x  [Mm*Dd];
__device__ float g_tmp[Mm*Dd];

__device__ __nv_bfloat16 x_h [Mm*Dd],  x_l [Mm*Dd];
__device__ __nv_bfloat16 o_h [Mm*Dd],  o_l [Mm*Dd];
__device__ __nv_bfloat16 h1_h[(size_t)Mm*DFF], h1_l[(size_t)Mm*DFF];
__device__ __nv_bfloat16 qkvp_h[(size_t)Mm*NQKV], qkvp_l[(size_t)Mm*NQKV];

__device__ __nv_bfloat16 wqkv_h[(size_t)Ll*Dd*NQKV], wqkv_l[(size_t)Ll*Dd*NQKV];
__device__ __nv_bfloat16 wpr_h [(size_t)Ll*Dd*Dd],   wpr_l [(size_t)Ll*Dd*Dd];
__device__ __nv_bfloat16 w1b_h [(size_t)Ll*Dd*DFF],  w1b_l [(size_t)Ll*Dd*DFF];
__device__ __nv_bfloat16 w2b_h [(size_t)Ll*DFF*Dd],  w2b_l [(size_t)Ll*DFF*Dd];
__device__ __nv_bfloat16 lmw_h [(size_t)Dd*VP],      lmw_l [(size_t)Dd*VP];

// ---------------- helpers --------------------------------------------------
__device__ __forceinline__ uint32_t s2u(const void* p) {
    uint32_t a;
    asm("{ .reg .u64 t; cvta.to.shared.u64 t, %1; cvt.u32.u64 %0, t; }" : "=r"(a) : "l"(p));
    return a;
}
__device__ __forceinline__ void cpa16(uint32_t dst, const void* src) {
    asm volatile("cp.async.cg.shared.global [%0], [%1], 16;" :: "r"(dst), "l"(src));
}
__device__ __forceinline__ void ldmx4(uint32_t* r, uint32_t addr) {
    asm volatile("ldmatrix.sync.aligned.m8n8.x4.shared.b16 {%0,%1,%2,%3},[%4];"
                 : "=r"(r[0]), "=r"(r[1]), "=r"(r[2]), "=r"(r[3]) : "r"(addr));
}
__device__ __forceinline__ void ldmx4t(uint32_t* r, uint32_t addr) {
    asm volatile("ldmatrix.sync.aligned.m8n8.x4.trans.shared.b16 {%0,%1,%2,%3},[%4];"
                 : "=r"(r[0]), "=r"(r[1]), "=r"(r[2]), "=r"(r[3]) : "r"(addr));
}
__device__ __forceinline__ void mma_bf16(float* c, const uint32_t* a,
                                         uint32_t b0, uint32_t b1) {
    asm volatile(
        "mma.sync.aligned.m16n8k16.row.col.f32.bf16.bf16.f32 "
        "{%0,%1,%2,%3},{%4,%5,%6,%7},{%8,%9},{%0,%1,%2,%3};"
        : "+f"(c[0]), "+f"(c[1]), "+f"(c[2]), "+f"(c[3])
        : "r"(a[0]), "r"(a[1]), "r"(a[2]), "r"(a[3]), "r"(b0), "r"(b1));
}
__device__ __forceinline__ void splitv(float v, __nv_bfloat16& h, __nv_bfloat16& l) {
    h = __float2bfloat16_rn(v);
    l = __float2bfloat16_rn(v - __bfloat162float(h));
}
__device__ __forceinline__ uint32_t pk(__nv_bfloat16 a, __nv_bfloat16 b) {
    return ((uint32_t)__bfloat16_as_ushort(b) << 16) | __bfloat16_as_ushort(a);
}
// split 4 floats -> packed hi uint2 / lo uint2
__device__ __forceinline__ void split4(float4 v, uint2& h, uint2& l) {
    __nv_bfloat16 h0, h1, h2, h3, l0, l1, l2, l3;
    splitv(v.x, h0, l0); splitv(v.y, h1, l1);
    splitv(v.z, h2, l2); splitv(v.w, h3, l3);
    h = make_uint2(pk(h0, h1), pk(h2, h3));
    l = make_uint2(pk(l0, l1), pk(l2, l3));
}

// ---------------- weight conversion (vectorized) ---------------------------
__global__ void split_flat(const float* __restrict__ src,
                           __nv_bfloat16* __restrict__ h,
                           __nv_bfloat16* __restrict__ l, size_t n4) {
    for (size_t i = (size_t)blockIdx.x * blockDim.x + threadIdx.x; i < n4;
         i += (size_t)gridDim.x * blockDim.x) {
        uint2 hp, lp;
        split4(((const float4*)src)[i], hp, lp);
        ((uint2*)h)[i] = hp;
        ((uint2*)l)[i] = lp;
    }
}
__global__ void conv_qkv(const float* __restrict__ wq,
                         const float* __restrict__ wk,
                         const float* __restrict__ wv) {
    const size_t total4 = (size_t)Ll * Dd * NQKV / 4;
    for (size_t i4 = (size_t)blockIdx.x * blockDim.x + threadIdx.x; i4 < total4;
         i4 += (size_t)gridDim.x * blockDim.x) {
        size_t e = i4 * 4;
        size_t l = e / ((size_t)Dd * NQKV);
        size_t r = e - l * ((size_t)Dd * NQKV);
        int k = (int)(r / NQKV);
        int n = (int)(r - (size_t)k * NQKV);
        int wsel = n / Dd;
        int r2 = n - wsel * Dd;
        int hh = r2 >> 6, s = r2 & 63;
        const float* base = (wsel == 0) ? wq : ((wsel == 1) ? wk : wv);
        float4 v = *(const float4*)(base + (((size_t)l * Hh + hh) * Dd + k) * HS + s);
        uint2 hp, lp;
        split4(v, hp, lp);
        ((uint2*)wqkv_h)[i4] = hp;
        ((uint2*)wqkv_l)[i4] = lp;
    }
}
__global__ void conv_lm(const float* __restrict__ lm_w) {
    const size_t total4 = (size_t)Dd * VP / 4;
    for (size_t i4 = (size_t)blockIdx.x * blockDim.x + threadIdx.x; i4 < total4;
         i4 += (size_t)gridDim.x * blockDim.x) {
        size_t e = i4 * 4;
        int k = (int)(e / VP);
        int n = (int)(e - (size_t)k * VP);
        const float* row = lm_w + (size_t)k * Vv;
        float4 v;
        v.x = (n     < Vv) ? row[n]     : 0.f;
        v.y = (n + 1 < Vv) ? row[n + 1] : 0.f;
        v.z = (n + 2 < Vv) ? row[n + 2] : 0.f;
        v.w = (n + 3 < Vv) ? row[n + 3] : 0.f;
        uint2 hp, lp;
        split4(v, hp, lp);
        ((uint2*)lmw_h)[i4] = hp;
        ((uint2*)lmw_l)[i4] = lp;
    }
}

// ---------------- bf16x3 tensor-core GEMM (cp.async double-buffered) -------
__global__ __launch_bounds__(256, 2) void gemm_bf3(
    const __nv_bfloat16* __restrict__ Ah_g, const __nv_bfloat16* __restrict__ Al_g,
    int lda,
    const __nv_bfloat16* __restrict__ Bh_g, const __nv_bfloat16* __restrict__ Bl_g,
    int ldb,
    const float* __restrict__ bias,
    float* __restrict__ Cf,
    __nv_bfloat16* __restrict__ Ch, __nv_bfloat16* __restrict__ Cl,
    int ldc, int N, int K, int relu, int outmode)
{
    extern __shared__ char smem[];
    const uint32_t sb = s2u(smem);
    const int tid = threadIdx.x;
    const int wid = tid >> 5, lane = tid & 31;
    const int m0 = blockIdx.x * TM;
    const int n0 = blockIdx.y * TN;
    const int mw = (wid & 3) * 32;
    const int nw = (wid >> 2) * 64;

    float acc[2][8][4];
    #pragma unroll
    for (int a = 0; a < 2; a++)
        #pragma unroll
        for (int b = 0; b < 8; b++)
            #pragma unroll
            for (int c = 0; c < 4; c++) acc[a][b][c] = 0.f;

    auto load_stage = [&](int kc, int st) {
        uint32_t base = sb + st * STAGE_BYTES;
        #pragma unroll
        for (int i = 0; i < 2; i++) {
            int c = tid + i * 256;
            int row = c >> 2, q = c & 3;
            uint32_t d = base + OFF_AH + row * 80 + q * 16;
            cpa16(d, Ah_g + (size_t)(m0 + row) * lda + kc + q * 8);
            cpa16(d + (OFF_AL - OFF_AH), Al_g + (size_t)(m0 + row) * lda + kc + q * 8);
        }
        #pragma unroll
        for (int i = 0; i < 2; i++) {
            int c = tid + i * 256;
            int row = c >> 4, q = c & 15;
            uint32_t d = base + OFF_BH + row * 272 + q * 16;
            cpa16(d, Bh_g + (size_t)(kc + row) * ldb + n0 + q * 8);
            cpa16(d + (OFF_BL - OFF_BH), Bl_g + (size_t)(kc + row) * ldb + n0 + q * 8);
        }
        asm volatile("cp.async.commit_group;" ::: "memory");
    };

    const int niter = K / BK;
    load_stage(0, 0);

    for (int it = 0; it < niter; it++) {
        if (it + 1 < niter) {
            load_stage((it + 1) * BK, (it + 1) & 1);
            asm volatile("cp.async.wait_group 1;" ::: "memory");
        } else {
            asm volatile("cp.async.wait_group 0;" ::: "memory");
        }
        __syncthreads();

        const uint32_t sbase = sb + (it & 1) * STAGE_BYTES;
        #pragma unroll
        for (int kk = 0; kk < BK; kk += 16) {
            uint32_t ah[2][4], al[2][4];
            int arow = mw + (lane & 15);
            int acol = kk + (lane >> 4) * 8;
            #pragma unroll
            for (int mi = 0; mi < 2; mi++) {
                uint32_t off = (uint32_t)(arow + mi * 16) * (SA_STRIDE * 2) + acol * 2;
                ldmx4(ah[mi], sbase + OFF_AH + off);
                ldmx4(al[mi], sbase + OFF_AL + off);
            }
            int brow = kk + (lane & 15);
            int bcol = nw + (lane >> 4) * 8;
            #pragma unroll
            for (int ni = 0; ni < 4; ni++) {
                uint32_t off = (uint32_t)brow * (SB_STRIDE * 2) + (bcol + ni * 16) * 2;
                uint32_t bh[4], bl[4];
                ldmx4t(bh, sbase + OFF_BH + off);
                ldmx4t(bl, sbase + OFF_BL + off);
                #pragma unroll
                for (int mi = 0; mi < 2; mi++) {
                    mma_bf16(acc[mi][2 * ni],     ah[mi], bh[0], bh[1]);
                    mma_bf16(acc[mi][2 * ni],     ah[mi], bl[0], bl[1]);
                    mma_bf16(acc[mi][2 * ni],     al[mi], bh[0], bh[1]);
                    mma_bf16(acc[mi][2 * ni + 1], ah[mi], bh[2], bh[3]);
                    mma_bf16(acc[mi][2 * ni + 1], ah[mi], bl[2], bl[3]);
                    mma_bf16(acc[mi][2 * ni + 1], al[mi], bh[2], bh[3]);
                }
            }
        }
        __syncthreads();
    }

    float* sC = (float*)smem;
    const int r0 = mw + (lane >> 2);
    const int c0 = 2 * (lane & 3);
    #pragma unroll 1
    for (int hf = 0; hf < 2; hf++) {
        if ((wid >> 2) == hf) {
            #pragma unroll
            for (int mi = 0; mi < 2; mi++)
                #pragma unroll
                for (int ni = 0; ni < 8; ni++) {
                    int rr = (r0 + mi * 16) * 68 + ni * 8 + c0;
                    sC[rr]              = acc[mi][ni][0];
                    sC[rr + 1]          = acc[mi][ni][1];
                    sC[rr + 8 * 68]     = acc[mi][ni][2];
                    sC[rr + 8 * 68 + 1] = acc[mi][ni][3];
                }
        }
        __syncthreads();
        #pragma unroll 4
        for (int it = 0; it < 32; it++) {
            int idx = tid + it * 256;
            int r = idx >> 6, c = idx & 63;
            int col = n0 + hf * 64 + c;
            if (col < N) {
                float v = sC[r * 68 + c];
                if (bias) v += bias[col];
                if (relu) v = fmaxf(v, 0.f);
                if (outmode == 0) {
                    Cf[(size_t)(m0 + r) * ldc + col] = v;
                } else {
                    __nv_bfloat16 hh, ll;
                    splitv(v, hh, ll);
                    Ch[(size_t)(m0 + r) * ldc + col] = hh;
                    Cl[(size_t)(m0 + r) * ldc + col] = ll;
                }
            }
        }
        __syncthreads();
    }
}

// ---------------- flash attention (bf16x3, causal, online softmax) ---------
// grid (8 t-tiles, B*H), 256 threads (8 warps x 16 rows).
__global__ __launch_bounds__(256) void flash_kernel() {
    extern __shared__ char smem[];
    const uint32_t sb = s2u(smem);
    const int tid = threadIdx.x, wid = tid >> 5, lane = tid & 31;
    const int bh = blockIdx.y;
    const int b = bh / Hh, h = bh % Hh;
    const int t0 = (int)(gridDim.x - 1 - blockIdx.x) * FBM;   // heavy tiles first
    const int mw = wid * 16;

    const size_t rowbase = (size_t)(b * Tt) * NQKV + h * HS;

    // ---- load Q tile [128][64] h/l into stage0, extract frags ----
    #pragma unroll
    for (int i = 0; i < 4; i++) {
        int c = tid + i * 256;
        int row = c >> 3, q = c & 7;
        size_t g = rowbase + (size_t)(t0 + row) * NQKV + q * 8;
        cpa16(sb + row * 144 + q * 16, qkvp_h + g);
        cpa16(sb + 18432 + row * 144 + q * 16, qkvp_l + g);
    }
    asm volatile("cp.async.commit_group;" ::: "memory");
    asm volatile("cp.async.wait_group 0;" ::: "memory");
    __syncthreads();

    uint32_t qfh[4][4], qfl[4][4];
    {
        int arow = mw + (lane & 15);
        #pragma unroll
        for (int kk = 0; kk < 4; kk++) {
            int acol = kk * 16 + (lane >> 4) * 8;
            uint32_t off = (uint32_t)arow * 144 + acol * 2;
            ldmx4(qfh[kk], sb + off);
            ldmx4(qfl[kk], sb + 18432 + off);
        }
    }
    __syncthreads();   // everyone done reading Q before stage0 is reused

    auto kv_issue = [&](int u0, int st) {
        uint32_t base = sb + st * FSTAGE;
        #pragma unroll
        for (int i = 0; i < 2; i++) {
            int c = tid + i * 256;
            int row = c >> 3, q = c & 7;
            size_t g = rowbase + (size_t)(u0 + row) * NQKV + q * 8;
            uint32_t d = base + row * 144 + q * 16;
            cpa16(d + FST_KH, qkvp_h + g + Dd);
            cpa16(d + FST_KL, qkvp_l + g + Dd);
            cpa16(d + FST_VH, qkvp_h + g + 2 * Dd);
            cpa16(d + FST_VL, qkvp_l + g + 2 * Dd);
        }
        asm volatile("cp.async.commit_group;" ::: "memory");
    };

    float o[8][4];
    #pragma unroll
    for (int i = 0; i < 8; i++)
        #pragma unroll
        for (int j = 0; j < 4; j++) o[i][j] = 0.f;
    float mA = -1e30f, mB = -1e30f, lA = 0.f, lB = 0.f;

    const int nt = t0 / FBN + 2;
    kv_issue(0, 1);

    for (int it = 0; it < nt; it++) {
        const int u0 = it * FBN;
        if (it + 1 < nt) {
            kv_issue((it + 1) * FBN, it & 1);
            asm volatile("cp.async.wait_group 1;" ::: "memory");
        } else {
            asm volatile("cp.async.wait_group 0;" ::: "memory");
        }
        __syncthreads();
        const uint32_t kb = sb + ((it + 1) & 1) * FSTAGE;

        // ---- S = Q K^T (3-pass) ----
        float s[8][4];
        #pragma unroll
        for (int i = 0; i < 8; i++)
            #pragma unroll
            for (int j = 0; j < 4; j++) s[i][j] = 0.f;

        // non-trans B-frag lane addressing on [n][k] storage
        const int bn = ((lane >> 4) << 3) + (lane & 7);
        const int bk = ((lane >> 3) & 1) * 8;
        #pragma unroll
        for (int kk = 0; kk < 4; kk++) {
            #pragma unroll
            for (int j = 0; j < 4; j++) {
                uint32_t addr = kb + (uint32_t)(j * 16 + bn) * 144 + (kk * 16 + bk) * 2;
                uint32_t kh4[4], kl4[4];
                ldmx4(kh4, addr + FST_KH);
                ldmx4(kl4, addr + FST_KL);
                mma_bf16(s[2 * j],     qfh[kk], kh4[0], kh4[1]);
                mma_bf16(s[2 * j],     qfh[kk], kl4[0], kl4[1]);
                mma_bf16(s[2 * j],     qfl[kk], kh4[0], kh4[1]);
                mma_bf16(s[2 * j + 1], qfh[kk], kh4[2], kh4[3]);
                mma_bf16(s[2 * j + 1], qfh[kk], kl4[2], kl4[3]);
                mma_bf16(s[2 * j + 1], qfl[kk], kh4[2], kh4[3]);
            }
        }

        // ---- scale + causal mask ----
        const int rA = lane >> 2;
        const int tA = t0 + mw + rA, tB = tA + 8;
        #pragma unroll
        for (int nb = 0; nb < 8; nb++)
            #pragma unroll
            for (int j = 0; j < 4; j++) s[nb][j] *= 0.125f;
        if (u0 + FBN - 1 > t0 + mw) {
            #pragma unroll
            for (int nb = 0; nb < 8; nb++) {
                int u_lo = u0 + nb * 8 + (lane & 3) * 2;
                if (u_lo     > tA) s[nb][0] = -1e30f;
                if (u_lo + 1 > tA) s[nb][1] = -1e30f;
                if (u_lo     > tB) s[nb][2] = -1e30f;
                if (u_lo + 1 > tB) s[nb][3] = -1e30f;
            }
        }

        // ---- online softmax ----
        float rmA = -1e30f, rmB = -1e30f;
        #pragma unroll
        for (int nb = 0; nb < 8; nb++) {
            rmA = fmaxf(rmA, fmaxf(s[nb][0], s[nb][1]));
            rmB = fmaxf(rmB, fmaxf(s[nb][2], s[nb][3]));
        }
        rmA = fmaxf(rmA, __shfl_xor_sync(0xffffffffu, rmA, 1));
        rmA = fmaxf(rmA, __shfl_xor_sync(0xffffffffu, rmA, 2));
        rmB = fmaxf(rmB, __shfl_xor_sync(0xffffffffu, rmB, 1));
        rmB = fmaxf(rmB, __shfl_xor_sync(0xffffffffu, rmB, 2));
        float mAn = fmaxf(mA, rmA), mBn = fmaxf(mB, rmB);
        float scA = __expf(mA - mAn), scB = __expf(mB - mBn);
        mA = mAn; mB = mBn;

        float rsA = 0.f, rsB = 0.f;
        #pragma unroll
        for (int nb = 0; nb < 8; nb++) {
            s[nb][0] = __expf(s[nb][0] - mA); rsA += s[nb][0];
            s[nb][1] = __expf(s[nb][1] - mA); rsA += s[nb][1];
            s[nb][2] = __expf(s[nb][2] - mB); rsB += s[nb][2];
            s[nb][3] = __expf(s[nb][3] - mB); rsB += s[nb][3];
        }
        rsA += __shfl_xor_sync(0xffffffffu, rsA, 1);
        rsA += __shfl_xor_sync(0xffffffffu, rsA, 2);
        rsB += __shfl_xor_sync(0xffffffffu, rsB, 1);
        rsB += __shfl_xor_sync(0xffffffffu, rsB, 2);
        lA = lA * scA + rsA;
        lB = lB * scB + rsB;
        #pragma unroll
        for (int nb = 0; nb < 8; nb++) {
            o[nb][0] *= scA; o[nb][1] *= scA;
            o[nb][2] *= scB; o[nb][3] *= scB;
        }

        // ---- O += P V (3-pass) ----
        #pragma unroll
        for (int g = 0; g < 4; g++) {
            uint32_t pha[4], pla[4];
            {
                __nv_bfloat16 h0, h1, l0, l1;
                splitv(s[2 * g][0], h0, l0); splitv(s[2 * g][1], h1, l1);
                pha[0] = pk(h0, h1); pla[0] = pk(l0, l1);
                splitv(s[2 * g][2], h0, l0); splitv(s[2 * g][3], h1, l1);
                pha[1] = pk(h0, h1); pla[1] = pk(l0, l1);
                splitv(s[2 * g + 1][0], h0, l0); splitv(s[2 * g + 1][1], h1, l1);
                pha[2] = pk(h0, h1); pla[2] = pk(l0, l1);
                splitv(s[2 * g + 1][2], h0, l0); splitv(s[2 * g + 1][3], h1, l1);
                pha[3] = pk(h0, h1); pla[3] = pk(l0, l1);
            }
            const int vrow = g * 16 + (lane & 15);
            #pragma unroll
            for (int j = 0; j < 4; j++) {
                uint32_t addr = kb + (uint32_t)vrow * 144 +
                                (uint32_t)(j * 16 + (lane >> 4) * 8) * 2;
                uint32_t vh4[4], vl4[4];
                ldmx4t(vh4, addr + FST_VH);
                ldmx4t(vl4, addr + FST_VL);
                mma_bf16(o[2 * j],     pha, vh4[0], vh4[1]);
                mma_bf16(o[2 * j],     pha, vl4[0], vl4[1]);
                mma_bf16(o[2 * j],     pla, vh4[0], vh4[1]);
                mma_bf16(o[2 * j + 1], pha, vh4[2], vh4[3]);
                mma_bf16(o[2 * j + 1], pha, vl4[2], vl4[3]);
                mma_bf16(o[2 * j + 1], pla, vh4[2], vh4[3]);
            }
        }
        __syncthreads();
    }

    // ---- finalize & store o hi/lo ----
    const float invA = 1.f / lA, invB = 1.f / lB;
    const int rA = lane >> 2;
    const int tA = t0 + mw + rA, tB = tA + 8;
    const int cbase = h * HS + (lane & 3) * 2;
    size_t baseA = (size_t)(b * Tt + tA) * Dd + cbase;
    size_t baseB = (size_t)(b * Tt + tB) * Dd + cbase;
    #pragma unroll
    for (int nb = 0; nb < 8; nb++) {
        splitv(o[nb][0] * invA, o_h[baseA + nb * 8],     o_l[baseA + nb * 8]);
        splitv(o[nb][1] * invA, o_h[baseA + nb * 8 + 1], o_l[baseA + nb * 8 + 1]);
        splitv(o[nb][2] * invB, o_h[baseB + nb * 8],     o_l[baseB + nb * 8]);
        splitv(o[nb][3] * invB, o_h[baseB + nb * 8 + 1], o_l[baseB + nb * 8 + 1]);
    }
}

// ---------------- reductions ------------------------------------------------
__device__ __forceinline__ float block_reduce_sum(float v, float* sh) {
    int tid = threadIdx.x;
    #pragma unroll
    for (int o = 16; o > 0; o >>= 1) v += __shfl_xor_sync(0xffffffffu, v, o);
    if ((tid & 31) == 0) sh[tid >> 5] = v;
    __syncthreads();
    if (tid < 32) {
        float x = (tid < (int)(blockDim.x >> 5)) ? sh[tid] : 0.f;
        #pragma unroll
        for (int o = 4; o > 0; o >>= 1) x += __shfl_xor_sync(0xffffffffu, x, o);
        if (tid == 0) sh[0] = x;
    }
    __syncthreads();
    float r = sh[0];
    __syncthreads();
    return r;
}

// ---------------- embedding -------------------------------------------------
__global__ void embed_kernel(const int* __restrict__ idx,
                             const float* __restrict__ tok_emb,
                             const float* __restrict__ pos_emb) {
    int m = blockIdx.x;
    int t = m % Tt;
    int tok = idx[m];
    const float* te = tok_emb + (size_t)tok * Dd;
    const float* pe = pos_emb + (size_t)t * Dd;
    float* x = g_x + (size_t)m * Dd;
    for (int c = threadIdx.x; c < Dd; c += blockDim.x) {
        float v = te[c] + pe[c];
        x[c] = v;
        splitv(v, x_h[(size_t)m * Dd + c], x_l[(size_t)m * Dd + c]);
    }
}

// ---------------- fused residual add + LayerNorm ----------------------------
__global__ void addln_kernel(const float* __restrict__ add,
                             const float* __restrict__ gamma,
                             const float* __restrict__ beta) {
    __shared__ float sh[8];
    int m = blockIdx.x;
    float* x = g_x + (size_t)m * Dd;
    const float* a = add + (size_t)m * Dd;
    int tid = threadIdx.x;

    float v[3];
    float s = 0.f;
    #pragma unroll
    for (int i = 0; i < 3; i++) {
        int c = tid + i * 256;
        v[i] = x[c] + a[c];
        s += v[i];
    }
    s = block_reduce_sum(s, sh);
    float mean = s * (1.f / Dd);

    float q = 0.f;
    #pragma unroll
    for (int i = 0; i < 3; i++) {
        float d = v[i] - mean;
        q += d * d;
    }
    q = block_reduce_sum(q, sh);
    float rstd = rsqrtf(q * (1.f / Dd) + 1e-5f);

    #pragma unroll
    for (int i = 0; i < 3; i++) {
        int c = tid + i * 256;
        float o = (v[i] - mean) * rstd * gamma[c] + beta[c];
        x[c] = o;
        splitv(o, x_h[(size_t)m * Dd + c], x_l[(size_t)m * Dd + c]);
    }
}

// ---------------- host orchestration ----------------------------------------
extern "C" void kernel_launch(void* const* d_in, const int* in_sizes, int n_in,
                              void* d_out, int out_size) {
    const int*   idx     = (const int*)  d_in[0];
    const float* tok_emb = (const float*)d_in[1];
    const float* pos_emb = (const float*)d_in[2];
    const float* wq      = (const float*)d_in[3];
    const float* wk      = (const float*)d_in[4];
    const float* wv      = (const float*)d_in[5];
    const float* wproj   = (const float*)d_in[6];
    const float* bproj   = (const float*)d_in[7];
    const float* w1      = (const float*)d_in[8];
    const float* b1      = (const float*)d_in[9];
    const float* w2      = (const float*)d_in[10];
    const float* b2      = (const float*)d_in[11];
    const float* ln1_g   = (const float*)d_in[12];
    const float* ln1_b   = (const float*)d_in[13];
    const float* ln2_g   = (const float*)d_in[14];
    const float* ln2_b   = (const float*)d_in[15];
    const float* lm_w    = (const float*)d_in[16];
    const float* lm_b    = (const float*)d_in[17];
    float* out = (float*)d_out;

    cudaFuncSetAttribute(gemm_bf3, cudaFuncAttributeMaxDynamicSharedMemorySize, GEMM_SMEM);
    cudaFuncSetAttribute(flash_kernel, cudaFuncAttributeMaxDynamicSharedMemorySize, FLASH_SMEM);

    float *p_x, *p_tmp;
    cudaGetSymbolAddress((void**)&p_x,   g_x);
    cudaGetSymbolAddress((void**)&p_tmp, g_tmp);
    __nv_bfloat16 *pxh, *pxl, *poh, *pol, *ph1h, *ph1l, *pqh, *pql;
    cudaGetSymbolAddress((void**)&pxh, x_h);   cudaGetSymbolAddress((void**)&pxl, x_l);
    cudaGetSymbolAddress((void**)&poh, o_h);   cudaGetSymbolAddress((void**)&pol, o_l);
    cudaGetSymbolAddress((void**)&ph1h, h1_h); cudaGetSymbolAddress((void**)&ph1l, h1_l);
    cudaGetSymbolAddress((void**)&pqh, qkvp_h); cudaGetSymbolAddress((void**)&pql, qkvp_l);
    __nv_bfloat16 *pwqh, *pwql, *pwph, *pwpl, *pw1h, *pw1l, *pw2h, *pw2l, *plmh, *plml;
    cudaGetSymbolAddress((void**)&pwqh, wqkv_h); cudaGetSymbolAddress((void**)&pwql, wqkv_l);
    cudaGetSymbolAddress((void**)&pwph, wpr_h);  cudaGetSymbolAddress((void**)&pwpl, wpr_l);
    cudaGetSymbolAddress((void**)&pw1h, w1b_h);  cudaGetSymbolAddress((void**)&pw1l, w1b_l);
    cudaGetSymbolAddress((void**)&pw2h, w2b_h);  cudaGetSymbolAddress((void**)&pw2l, w2b_l);
    cudaGetSymbolAddress((void**)&plmh, lmw_h);  cudaGetSymbolAddress((void**)&plml, lmw_l);

    conv_qkv<<<2048, 256>>>(wq, wk, wv);
    split_flat<<<1024, 256>>>(wproj, pwph, pwpl, (size_t)Ll * Dd * Dd / 4);
    split_flat<<<2048, 256>>>(w1, pw1h, pw1l, (size_t)Ll * Dd * DFF / 4);
    split_flat<<<2048, 256>>>(w2, pw2h, pw2l, (size_t)Ll * DFF * Dd / 4);
    conv_lm<<<4096, 256>>>(lm_w);

    embed_kernel<<<Mm, 256>>>(idx, tok_emb, pos_emb);

    for (int l = 0; l < Ll; l++) {
        // QKV -> bf16 hi/lo pairs
        gemm_bf3<<<dim3(Mm / TM, NQKV / TN), 256, GEMM_SMEM>>>(
            pxh, pxl, Dd,
            pwqh + (size_t)l * Dd * NQKV, pwql + (size_t)l * Dd * NQKV, NQKV,
            nullptr, nullptr, pqh, pql, NQKV, NQKV, Dd, 0, 1);
        // fused flash attention -> o hi/lo
        flash_kernel<<<dim3(Tt / FBM, Bq * Hh), 256, FLASH_SMEM>>>();
        // proj -> fp32 tmp
        gemm_bf3<<<dim3(Mm / TM, Dd / TN), 256, GEMM_SMEM>>>(
            poh, pol, Dd,
            pwph + (size_t)l * Dd * Dd, pwpl + (size_t)l * Dd * Dd, Dd,
            bproj + (size_t)l * Dd, p_tmp, nullptr, nullptr, Dd, Dd, Dd, 0, 0);
        addln_kernel<<<Mm, 256>>>(p_tmp, ln1_g + (size_t)l * Dd, ln1_b + (size_t)l * Dd);
        // fc1 -> bf16 pair + relu
        gemm_bf3<<<dim3(Mm / TM, DFF / TN), 256, GEMM_SMEM>>>(
            pxh, pxl, Dd,
            pw1h + (size_t)l * Dd * DFF, pw1l + (size_t)l * Dd * DFF, DFF,
            b1 + (size_t)l * DFF, nullptr, ph1h, ph1l, DFF, DFF, Dd, 1, 1);
        // fc2 -> fp32 tmp
        gemm_bf3<<<dim3(Mm / TM, Dd / TN), 256, GEMM_SMEM>>>(
            ph1h, ph1l, DFF,
            pw2h + (size_t)l * DFF * Dd, pw2l + (size_t)l * DFF * Dd, Dd,
            b2 + (size_t)l * Dd, p_tmp, nullptr, nullptr, Dd, Dd, DFF, 0, 0);
        addln_kernel<<<Mm, 256>>>(p_tmp, ln2_g + (size_t)l * Dd, ln2_b + (size_t)l * Dd);
    }

    gemm_bf3<<<dim3(Mm / TM, VP / TN), 256, GEMM_SMEM>>>(
        pxh, pxl, Dd, plmh, plml, VP,
        lm_b, out, nullptr, nullptr, Vv, Vv, Dd, 0, 0);
}

// round 7
// speedup vs baseline: 3.8286x; 1.0114x over previous
#include <cuda_runtime.h>
#include <cuda_bf16.h>
#include <cstdint>
#include <math.h>
#include <stddef.h>

// Problem constants
#define Bq 2
#define Tt 1024
#define Dd 768
#define Hh 12
#define Ll 6
#define Vv 50257
#define VP 50304
#define HS 64
#define Mm (Bq*Tt)
#define DFF (4*Dd)
#define NQKV (3*Dd)

// GEMM tiling
#define TM 128
#define TN 128
#define BK 32
#define SA_STRIDE 40
#define SB_STRIDE 136
#define OFF_AH 0
#define OFF_AL 10240
#define OFF_BH 20480
#define OFF_BL 29184
#define STAGE_BYTES 37888
#define GEMM_SMEM (2*STAGE_BYTES)

// Flash attention tiling (FBM=64, 128 threads, 4 warps)
#define FBM 64
#define FBN 64
#define FST_KH 0
#define FST_KL 9216
#define FST_VH 18432
#define FST_VL 27648
#define FSTAGE 36864
#define FLASH_SMEM (2*FSTAGE)   // 73728 -> 3 CTAs/SM

// ---------------- scratch --------------------------------------------------
__device__ float g_x  [Mm*Dd];
__device__ float g_tmp[Mm*Dd];

__device__ __nv_bfloat16 x_h [Mm*Dd],  x_l [Mm*Dd];
__device__ __nv_bfloat16 o_h [Mm*Dd],  o_l [Mm*Dd];
__device__ __nv_bfloat16 h1_h[(size_t)Mm*DFF], h1_l[(size_t)Mm*DFF];
__device__ __nv_bfloat16 qkvp_h[(size_t)Mm*NQKV], qkvp_l[(size_t)Mm*NQKV];

__device__ __nv_bfloat16 wqkv_h[(size_t)Ll*Dd*NQKV], wqkv_l[(size_t)Ll*Dd*NQKV];
__device__ __nv_bfloat16 wpr_h [(size_t)Ll*Dd*Dd],   wpr_l [(size_t)Ll*Dd*Dd];
__device__ __nv_bfloat16 w1b_h [(size_t)Ll*Dd*DFF],  w1b_l [(size_t)Ll*Dd*DFF];
__device__ __nv_bfloat16 w2b_h [(size_t)Ll*DFF*Dd],  w2b_l [(size_t)Ll*DFF*Dd];
__device__ __nv_bfloat16 lmw_h [(size_t)Dd*VP],      lmw_l [(size_t)Dd*VP];

// ---------------- helpers --------------------------------------------------
__device__ __forceinline__ uint32_t s2u(const void* p) {
    uint32_t a;
    asm("{ .reg .u64 t; cvta.to.shared.u64 t, %1; cvt.u32.u64 %0, t; }" : "=r"(a) : "l"(p));
    return a;
}
__device__ __forceinline__ void cpa16(uint32_t dst, const void* src) {
    asm volatile("cp.async.cg.shared.global [%0], [%1], 16;" :: "r"(dst), "l"(src));
}
__device__ __forceinline__ void ldmx4(uint32_t* r, uint32_t addr) {
    asm volatile("ldmatrix.sync.aligned.m8n8.x4.shared.b16 {%0,%1,%2,%3},[%4];"
                 : "=r"(r[0]), "=r"(r[1]), "=r"(r[2]), "=r"(r[3]) : "r"(addr));
}
__device__ __forceinline__ void ldmx4t(uint32_t* r, uint32_t addr) {
    asm volatile("ldmatrix.sync.aligned.m8n8.x4.trans.shared.b16 {%0,%1,%2,%3},[%4];"
                 : "=r"(r[0]), "=r"(r[1]), "=r"(r[2]), "=r"(r[3]) : "r"(addr));
}
__device__ __forceinline__ void mma_bf16(float* c, const uint32_t* a,
                                         uint32_t b0, uint32_t b1) {
    asm volatile(
        "mma.sync.aligned.m16n8k16.row.col.f32.bf16.bf16.f32 "
        "{%0,%1,%2,%3},{%4,%5,%6,%7},{%8,%9},{%0,%1,%2,%3};"
        : "+f"(c[0]), "+f"(c[1]), "+f"(c[2]), "+f"(c[3])
        : "r"(a[0]), "r"(a[1]), "r"(a[2]), "r"(a[3]), "r"(b0), "r"(b1));
}
__device__ __forceinline__ void splitv(float v, __nv_bfloat16& h, __nv_bfloat16& l) {
    h = __float2bfloat16_rn(v);
    l = __float2bfloat16_rn(v - __bfloat162float(h));
}
__device__ __forceinline__ uint32_t pk(__nv_bfloat16 a, __nv_bfloat16 b) {
    return ((uint32_t)__bfloat16_as_ushort(b) << 16) | __bfloat16_as_ushort(a);
}
__device__ __forceinline__ void split4(float4 v, uint2& h, uint2& l) {
    __nv_bfloat16 h0, h1, h2, h3, l0, l1, l2, l3;
    splitv(v.x, h0, l0); splitv(v.y, h1, l1);
    splitv(v.z, h2, l2); splitv(v.w, h3, l3);
    h = make_uint2(pk(h0, h1), pk(h2, h3));
    l = make_uint2(pk(l0, l1), pk(l2, l3));
}

// ---------------- weight conversion (uint32 math, MLP=2) -------------------
__global__ void split_flat(const float4* __restrict__ src,
                           uint2* __restrict__ h,
                           uint2* __restrict__ l, unsigned n4) {
    unsigned stride = gridDim.x * blockDim.x;
    for (unsigned i = blockIdx.x * blockDim.x + threadIdx.x; i < n4; i += 2 * stride) {
        unsigned j = i + stride;
        float4 a = src[i];
        float4 b;
        bool has2 = (j < n4);
        if (has2) b = src[j];
        uint2 ha, la;
        split4(a, ha, la);
        h[i] = ha; l[i] = la;
        if (has2) {
            uint2 hb, lb;
            split4(b, hb, lb);
            h[j] = hb; l[j] = lb;
        }
    }
}

__device__ __forceinline__ void qkv_one(const float* __restrict__ wq,
                                        const float* __restrict__ wk,
                                        const float* __restrict__ wv,
                                        unsigned i4) {
    unsigned e = i4 * 4u;
    unsigned l = e / (unsigned)(Dd * NQKV);
    unsigned r = e - l * (unsigned)(Dd * NQKV);
    unsigned k = r / (unsigned)NQKV;
    unsigned n = r - k * (unsigned)NQKV;
    unsigned wsel = n / (unsigned)Dd;
    unsigned r2 = n - wsel * (unsigned)Dd;
    unsigned hh = r2 >> 6, s = r2 & 63;
    const float* base = (wsel == 0) ? wq : ((wsel == 1) ? wk : wv);
    float4 v = *(const float4*)(base + ((size_t)(l * Hh + hh) * Dd + k) * HS + s);
    uint2 hp, lp;
    split4(v, hp, lp);
    ((uint2*)wqkv_h)[i4] = hp;
    ((uint2*)wqkv_l)[i4] = lp;
}
__global__ void conv_qkv(const float* __restrict__ wq,
                         const float* __restrict__ wk,
                         const float* __restrict__ wv) {
    const unsigned total4 = (unsigned)Ll * Dd * NQKV / 4u;
    unsigned stride = gridDim.x * blockDim.x;
    for (unsigned i = blockIdx.x * blockDim.x + threadIdx.x; i < total4; i += 2 * stride) {
        qkv_one(wq, wk, wv, i);
        if (i + stride < total4) qkv_one(wq, wk, wv, i + stride);
    }
}

__device__ __forceinline__ void lm_one(const float* __restrict__ lm_w, unsigned i4) {
    unsigned e = i4 * 4u;
    unsigned k = e / (unsigned)VP;
    unsigned n = e - k * (unsigned)VP;
    const float* row = lm_w + (size_t)k * Vv;
    float4 v;
    v.x = (n     < Vv) ? row[n]     : 0.f;
    v.y = (n + 1 < Vv) ? row[n + 1] : 0.f;
    v.z = (n + 2 < Vv) ? row[n + 2] : 0.f;
    v.w = (n + 3 < Vv) ? row[n + 3] : 0.f;
    uint2 hp, lp;
    split4(v, hp, lp);
    ((uint2*)lmw_h)[i4] = hp;
    ((uint2*)lmw_l)[i4] = lp;
}
__global__ void conv_lm(const float* __restrict__ lm_w) {
    const unsigned total4 = (unsigned)Dd * VP / 4u;
    unsigned stride = gridDim.x * blockDim.x;
    for (unsigned i = blockIdx.x * blockDim.x + threadIdx.x; i < total4; i += 2 * stride) {
        lm_one(lm_w, i);
        if (i + stride < total4) lm_one(lm_w, i + stride);
    }
}

// ---------------- bf16x3 tensor-core GEMM (cp.async double-buffered) -------
__global__ __launch_bounds__(256, 2) void gemm_bf3(
    const __nv_bfloat16* __restrict__ Ah_g, const __nv_bfloat16* __restrict__ Al_g,
    int lda,
    const __nv_bfloat16* __restrict__ Bh_g, const __nv_bfloat16* __restrict__ Bl_g,
    int ldb,
    const float* __restrict__ bias,
    float* __restrict__ Cf,
    __nv_bfloat16* __restrict__ Ch, __nv_bfloat16* __restrict__ Cl,
    int ldc, int N, int K, int relu, int outmode)
{
    extern __shared__ char smem[];
    const uint32_t sb = s2u(smem);
    const int tid = threadIdx.x;
    const int wid = tid >> 5, lane = tid & 31;
    const int m0 = blockIdx.x * TM;
    const int n0 = blockIdx.y * TN;
    const int mw = (wid & 3) * 32;
    const int nw = (wid >> 2) * 64;

    float acc[2][8][4];
    #pragma unroll
    for (int a = 0; a < 2; a++)
        #pragma unroll
        for (int b = 0; b < 8; b++)
            #pragma unroll
            for (int c = 0; c < 4; c++) acc[a][b][c] = 0.f;

    auto load_stage = [&](int kc, int st) {
        uint32_t base = sb + st * STAGE_BYTES;
        #pragma unroll
        for (int i = 0; i < 2; i++) {
            int c = tid + i * 256;
            int row = c >> 2, q = c & 3;
            uint32_t d = base + OFF_AH + row * 80 + q * 16;
            cpa16(d, Ah_g + (size_t)(m0 + row) * lda + kc + q * 8);
            cpa16(d + (OFF_AL - OFF_AH), Al_g + (size_t)(m0 + row) * lda + kc + q * 8);
        }
        #pragma unroll
        for (int i = 0; i < 2; i++) {
            int c = tid + i * 256;
            int row = c >> 4, q = c & 15;
            uint32_t d = base + OFF_BH + row * 272 + q * 16;
            cpa16(d, Bh_g + (size_t)(kc + row) * ldb + n0 + q * 8);
            cpa16(d + (OFF_BL - OFF_BH), Bl_g + (size_t)(kc + row) * ldb + n0 + q * 8);
        }
        asm volatile("cp.async.commit_group;" ::: "memory");
    };

    const int niter = K / BK;
    load_stage(0, 0);

    for (int it = 0; it < niter; it++) {
        if (it + 1 < niter) {
            load_stage((it + 1) * BK, (it + 1) & 1);
            asm volatile("cp.async.wait_group 1;" ::: "memory");
        } else {
            asm volatile("cp.async.wait_group 0;" ::: "memory");
        }
        __syncthreads();

        const uint32_t sbase = sb + (it & 1) * STAGE_BYTES;
        #pragma unroll
        for (int kk = 0; kk < BK; kk += 16) {
            uint32_t ah[2][4], al[2][4];
            int arow = mw + (lane & 15);
            int acol = kk + (lane >> 4) * 8;
            #pragma unroll
            for (int mi = 0; mi < 2; mi++) {
                uint32_t off = (uint32_t)(arow + mi * 16) * (SA_STRIDE * 2) + acol * 2;
                ldmx4(ah[mi], sbase + OFF_AH + off);
                ldmx4(al[mi], sbase + OFF_AL + off);
            }
            int brow = kk + (lane & 15);
            int bcol = nw + (lane >> 4) * 8;
            #pragma unroll
            for (int ni = 0; ni < 4; ni++) {
                uint32_t off = (uint32_t)brow * (SB_STRIDE * 2) + (bcol + ni * 16) * 2;
                uint32_t bh[4], bl[4];
                ldmx4t(bh, sbase + OFF_BH + off);
                ldmx4t(bl, sbase + OFF_BL + off);
                #pragma unroll
                for (int mi = 0; mi < 2; mi++) {
                    mma_bf16(acc[mi][2 * ni],     ah[mi], bh[0], bh[1]);
                    mma_bf16(acc[mi][2 * ni],     ah[mi], bl[0], bl[1]);
                    mma_bf16(acc[mi][2 * ni],     al[mi], bh[0], bh[1]);
                    mma_bf16(acc[mi][2 * ni + 1], ah[mi], bh[2], bh[3]);
                    mma_bf16(acc[mi][2 * ni + 1], ah[mi], bl[2], bl[3]);
                    mma_bf16(acc[mi][2 * ni + 1], al[mi], bh[2], bh[3]);
                }
            }
        }
        __syncthreads();
    }

    float* sC = (float*)smem;
    const int r0 = mw + (lane >> 2);
    const int c0 = 2 * (lane & 3);
    #pragma unroll 1
    for (int hf = 0; hf < 2; hf++) {
        if ((wid >> 2) == hf) {
            #pragma unroll
            for (int mi = 0; mi < 2; mi++)
                #pragma unroll
                for (int ni = 0; ni < 8; ni++) {
                    int rr = (r0 + mi * 16) * 68 + ni * 8 + c0;
                    sC[rr]              = acc[mi][ni][0];
                    sC[rr + 1]          = acc[mi][ni][1];
                    sC[rr + 8 * 68]     = acc[mi][ni][2];
                    sC[rr + 8 * 68 + 1] = acc[mi][ni][3];
                }
        }
        __syncthreads();
        #pragma unroll 4
        for (int it = 0; it < 32; it++) {
            int idx = tid + it * 256;
            int r = idx >> 6, c = idx & 63;
            int col = n0 + hf * 64 + c;
            if (col < N) {
                float v = sC[r * 68 + c];
                if (bias) v += bias[col];
                if (relu) v = fmaxf(v, 0.f);
                if (outmode == 0) {
                    Cf[(size_t)(m0 + r) * ldc + col] = v;
                } else {
                    __nv_bfloat16 hh, ll;
                    splitv(v, hh, ll);
                    Ch[(size_t)(m0 + r) * ldc + col] = hh;
                    Cl[(size_t)(m0 + r) * ldc + col] = ll;
                }
            }
        }
        __syncthreads();
    }
}

// ---------------- flash attention (bf16x3, causal, online softmax) ---------
// grid (16 t-tiles, B*H), 128 threads (4 warps x 16 rows).
__global__ __launch_bounds__(128) void flash_kernel() {
    extern __shared__ char smem[];
    const uint32_t sb = s2u(smem);
    const int tid = threadIdx.x, wid = tid >> 5, lane = tid & 31;
    const int bh = blockIdx.y;
    const int b = bh / Hh, h = bh % Hh;
    const int t0 = (int)(gridDim.x - 1 - blockIdx.x) * FBM;   // heavy tiles first
    const int mw = wid * 16;

    const size_t rowbase = (size_t)(b * Tt) * NQKV + h * HS;

    // ---- load Q tile [64][64] h/l into stage0, extract frags ----
    #pragma unroll
    for (int i = 0; i < 4; i++) {
        int c = tid + i * 128;
        int row = c >> 3, q = c & 7;
        size_t g = rowbase + (size_t)(t0 + row) * NQKV + q * 8;
        cpa16(sb + row * 144 + q * 16, qkvp_h + g);
        cpa16(sb + 9216 + row * 144 + q * 16, qkvp_l + g);
    }
    asm volatile("cp.async.commit_group;" ::: "memory");
    asm volatile("cp.async.wait_group 0;" ::: "memory");
    __syncthreads();

    uint32_t qfh[4][4], qfl[4][4];
    {
        int arow = mw + (lane & 15);
        #pragma unroll
        for (int kk = 0; kk < 4; kk++) {
            int acol = kk * 16 + (lane >> 4) * 8;
            uint32_t off = (uint32_t)arow * 144 + acol * 2;
            ldmx4(qfh[kk], sb + off);
            ldmx4(qfl[kk], sb + 9216 + off);
        }
    }
    __syncthreads();

    auto kv_issue = [&](int u0, int st) {
        uint32_t base = sb + st * FSTAGE;
        #pragma unroll
        for (int i = 0; i < 4; i++) {
            int c = tid + i * 128;
            int row = c >> 3, q = c & 7;
            size_t g = rowbase + (size_t)(u0 + row) * NQKV + q * 8;
            uint32_t d = base + row * 144 + q * 16;
            cpa16(d + FST_KH, qkvp_h + g + Dd);
            cpa16(d + FST_KL, qkvp_l + g + Dd);
            cpa16(d + FST_VH, qkvp_h + g + 2 * Dd);
            cpa16(d + FST_VL, qkvp_l + g + 2 * Dd);
        }
        asm volatile("cp.async.commit_group;" ::: "memory");
    };

    float o[8][4];
    #pragma unroll
    for (int i = 0; i < 8; i++)
        #pragma unroll
        for (int j = 0; j < 4; j++) o[i][j] = 0.f;
    float mA = -1e30f, mB = -1e30f, lA = 0.f, lB = 0.f;

    const int nt = t0 / FBN + 1;
    kv_issue(0, 1);

    for (int it = 0; it < nt; it++) {
        const int u0 = it * FBN;
        if (it + 1 < nt) {
            kv_issue((it + 1) * FBN, it & 1);
            asm volatile("cp.async.wait_group 1;" ::: "memory");
        } else {
            asm volatile("cp.async.wait_group 0;" ::: "memory");
        }
        __syncthreads();
        const uint32_t kb = sb + ((it + 1) & 1) * FSTAGE;

        // ---- S = Q K^T (3-pass) ----
        float s[8][4];
        #pragma unroll
        for (int i = 0; i < 8; i++)
            #pragma unroll
            for (int j = 0; j < 4; j++) s[i][j] = 0.f;

        const int bn = ((lane >> 4) << 3) + (lane & 7);
        const int bk = ((lane >> 3) & 1) * 8;
        #pragma unroll
        for (int kk = 0; kk < 4; kk++) {
            #pragma unroll
            for (int j = 0; j < 4; j++) {
                uint32_t addr = kb + (uint32_t)(j * 16 + bn) * 144 + (kk * 16 + bk) * 2;
                uint32_t kh4[4], kl4[4];
                ldmx4(kh4, addr + FST_KH);
                ldmx4(kl4, addr + FST_KL);
                mma_bf16(s[2 * j],     qfh[kk], kh4[0], kh4[1]);
                mma_bf16(s[2 * j],     qfh[kk], kl4[0], kl4[1]);
                mma_bf16(s[2 * j],     qfl[kk], kh4[0], kh4[1]);
                mma_bf16(s[2 * j + 1], qfh[kk], kh4[2], kh4[3]);
                mma_bf16(s[2 * j + 1], qfh[kk], kl4[2], kl4[3]);
                mma_bf16(s[2 * j + 1], qfl[kk], kh4[2], kh4[3]);
            }
        }

        // ---- scale + causal mask ----
        const int rA = lane >> 2;
        const int tA = t0 + mw + rA, tB = tA + 8;
        #pragma unroll
        for (int nb = 0; nb < 8; nb++)
            #pragma unroll
            for (int j = 0; j < 4; j++) s[nb][j] *= 0.125f;
        if (u0 + FBN - 1 > t0 + mw) {
            #pragma unroll
            for (int nb = 0; nb < 8; nb++) {
                int u_lo = u0 + nb * 8 + (lane & 3) * 2;
                if (u_lo     > tA) s[nb][0] = -1e30f;
                if (u_lo + 1 > tA) s[nb][1] = -1e30f;
                if (u_lo     > tB) s[nb][2] = -1e30f;
                if (u_lo + 1 > tB) s[nb][3] = -1e30f;
            }
        }

        // ---- online softmax ----
        float rmA = -1e30f, rmB = -1e30f;
        #pragma unroll
        for (int nb = 0; nb < 8; nb++) {
            rmA = fmaxf(rmA, fmaxf(s[nb][0], s[nb][1]));
            rmB = fmaxf(rmB, fmaxf(s[nb][2], s[nb][3]));
        }
        rmA = fmaxf(rmA, __shfl_xor_sync(0xffffffffu, rmA, 1));
        rmA = fmaxf(rmA, __shfl_xor_sync(0xffffffffu, rmA, 2));
        rmB = fmaxf(rmB, __shfl_xor_sync(0xffffffffu, rmB, 1));
        rmB = fmaxf(rmB, __shfl_xor_sync(0xffffffffu, rmB, 2));
        float mAn = fmaxf(mA, rmA), mBn = fmaxf(mB, rmB);
        float scA = __expf(mA - mAn), scB = __expf(mB - mBn);
        mA = mAn; mB = mBn;

        float rsA = 0.f, rsB = 0.f;
        #pragma unroll
        for (int nb = 0; nb < 8; nb++) {
            s[nb][0] = __expf(s[nb][0] - mA); rsA += s[nb][0];
            s[nb][1] = __expf(s[nb][1] - mA); rsA += s[nb][1];
            s[nb][2] = __expf(s[nb][2] - mB); rsB += s[nb][2];
            s[nb][3] = __expf(s[nb][3] - mB); rsB += s[nb][3];
        }
        rsA += __shfl_xor_sync(0xffffffffu, rsA, 1);
        rsA += __shfl_xor_sync(0xffffffffu, rsA, 2);
        rsB += __shfl_xor_sync(0xffffffffu, rsB, 1);
        rsB += __shfl_xor_sync(0xffffffffu, rsB, 2);
        lA = lA * scA + rsA;
        lB = lB * scB + rsB;
        #pragma unroll
        for (int nb = 0; nb < 8; nb++) {
            o[nb][0] *= scA; o[nb][1] *= scA;
            o[nb][2] *= scB; o[nb][3] *= scB;
        }

        // ---- O += P V (3-pass) ----
        #pragma unroll
        for (int g = 0; g < 4; g++) {
            uint32_t pha[4], pla[4];
            {
                __nv_bfloat16 h0, h1, l0, l1;
                splitv(s[2 * g][0], h0, l0); splitv(s[2 * g][1], h1, l1);
                pha[0] = pk(h0, h1); pla[0] = pk(l0, l1);
                splitv(s[2 * g][2], h0, l0); splitv(s[2 * g][3], h1, l1);
                pha[1] = pk(h0, h1); pla[1] = pk(l0, l1);
                splitv(s[2 * g + 1][0], h0, l0); splitv(s[2 * g + 1][1], h1, l1);
                pha[2] = pk(h0, h1); pla[2] = pk(l0, l1);
                splitv(s[2 * g + 1][2], h0, l0); splitv(s[2 * g + 1][3], h1, l1);
                pha[3] = pk(h0, h1); pla[3] = pk(l0, l1);
            }
            const int vrow = g * 16 + (lane & 15);
            #pragma unroll
            for (int j = 0; j < 4; j++) {
                uint32_t addr = kb + (uint32_t)vrow * 144 +
                                (uint32_t)(j * 16 + (lane >> 4) * 8) * 2;
                uint32_t vh4[4], vl4[4];
                ldmx4t(vh4, addr + FST_VH);
                ldmx4t(vl4, addr + FST_VL);
                mma_bf16(o[2 * j],     pha, vh4[0], vh4[1]);
                mma_bf16(o[2 * j],     pha, vl4[0], vl4[1]);
                mma_bf16(o[2 * j],     pla, vh4[0], vh4[1]);
                mma_bf16(o[2 * j + 1], pha, vh4[2], vh4[3]);
                mma_bf16(o[2 * j + 1], pha, vl4[2], vl4[3]);
                mma_bf16(o[2 * j + 1], pla, vh4[2], vh4[3]);
            }
        }
        __syncthreads();
    }

    // ---- finalize & store o hi/lo ----
    const float invA = 1.f / lA, invB = 1.f / lB;
    const int rA = lane >> 2;
    const int tA = t0 + mw + rA, tB = tA + 8;
    const int cbase = h * HS + (lane & 3) * 2;
    size_t baseA = (size_t)(b * Tt + tA) * Dd + cbase;
    size_t baseB = (size_t)(b * Tt + tB) * Dd + cbase;
    #pragma unroll
    for (int nb = 0; nb < 8; nb++) {
        splitv(o[nb][0] * invA, o_h[baseA + nb * 8],     o_l[baseA + nb * 8]);
        splitv(o[nb][1] * invA, o_h[baseA + nb * 8 + 1], o_l[baseA + nb * 8 + 1]);
        splitv(o[nb][2] * invB, o_h[baseB + nb * 8],     o_l[baseB + nb * 8]);
        splitv(o[nb][3] * invB, o_h[baseB + nb * 8 + 1], o_l[baseB + nb * 8 + 1]);
    }
}

// ---------------- embedding -------------------------------------------------
__global__ void embed_kernel(const int* __restrict__ idx,
                             const float* __restrict__ tok_emb,
                             const float* __restrict__ pos_emb) {
    int m = blockIdx.x;
    int t = m % Tt;
    int tok = idx[m];
    const float* te = tok_emb + (size_t)tok * Dd;
    const float* pe = pos_emb + (size_t)t * Dd;
    float* x = g_x + (size_t)m * Dd;
    for (int c = threadIdx.x; c < Dd; c += blockDim.x) {
        float v = te[c] + pe[c];
        x[c] = v;
        splitv(v, x_h[(size_t)m * Dd + c], x_l[(size_t)m * Dd + c]);
    }
}

// ---------------- fused residual add + LayerNorm (warp per row) ------------
__global__ void addln_kernel(const float* __restrict__ add,
                             const float* __restrict__ gamma,
                             const float* __restrict__ beta) {
    int row = blockIdx.x * (blockDim.x >> 5) + (threadIdx.x >> 5);
    int lane = threadIdx.x & 31;
    float* x = g_x + (size_t)row * Dd;
    const float* a = add + (size_t)row * Dd;

    float v[24];
    float s = 0.f;
    #pragma unroll
    for (int i = 0; i < 24; i++) {
        int c = lane + i * 32;
        v[i] = x[c] + a[c];
        s += v[i];
    }
    #pragma unroll
    for (int o = 16; o > 0; o >>= 1) s += __shfl_xor_sync(0xffffffffu, s, o);
    float mean = s * (1.f / Dd);

    float q = 0.f;
    #pragma unroll
    for (int i = 0; i < 24; i++) {
        float d = v[i] - mean;
        q += d * d;
    }
    #pragma unroll
    for (int o = 16; o > 0; o >>= 1) q += __shfl_xor_sync(0xffffffffu, q, o);
    float rstd = rsqrtf(q * (1.f / Dd) + 1e-5f);

    #pragma unroll
    for (int i = 0; i < 24; i++) {
        int c = lane + i * 32;
        float ov = (v[i] - mean) * rstd * gamma[c] + beta[c];
        x[c] = ov;
        splitv(ov, x_h[(size_t)row * Dd + c], x_l[(size_t)row * Dd + c]);
    }
}

// ---------------- host orchestration ----------------------------------------
extern "C" void kernel_launch(void* const* d_in, const int* in_sizes, int n_in,
                              void* d_out, int out_size) {
    const int*   idx     = (const int*)  d_in[0];
    const float* tok_emb = (const float*)d_in[1];
    const float* pos_emb = (const float*)d_in[2];
    const float* wq      = (const float*)d_in[3];
    const float* wk      = (const float*)d_in[4];
    const float* wv      = (const float*)d_in[5];
    const float* wproj   = (const float*)d_in[6];
    const float* bproj   = (const float*)d_in[7];
    const float* w1      = (const float*)d_in[8];
    const float* b1      = (const float*)d_in[9];
    const float* w2      = (const float*)d_in[10];
    const float* b2      = (const float*)d_in[11];
    const float* ln1_g   = (const float*)d_in[12];
    const float* ln1_b   = (const float*)d_in[13];
    const float* ln2_g   = (const float*)d_in[14];
    const float* ln2_b   = (const float*)d_in[15];
    const float* lm_w    = (const float*)d_in[16];
    const float* lm_b    = (const float*)d_in[17];
    float* out = (float*)d_out;

    cudaFuncSetAttribute(gemm_bf3, cudaFuncAttributeMaxDynamicSharedMemorySize, GEMM_SMEM);
    cudaFuncSetAttribute(flash_kernel, cudaFuncAttributeMaxDynamicSharedMemorySize, FLASH_SMEM);

    float *p_x, *p_tmp;
    cudaGetSymbolAddress((void**)&p_x,   g_x);
    cudaGetSymbolAddress((void**)&p_tmp, g_tmp);
    __nv_bfloat16 *pxh, *pxl, *poh, *pol, *ph1h, *ph1l, *pqh, *pql;
    cudaGetSymbolAddress((void**)&pxh, x_h);   cudaGetSymbolAddress((void**)&pxl, x_l);
    cudaGetSymbolAddress((void**)&poh, o_h);   cudaGetSymbolAddress((void**)&pol, o_l);
    cudaGetSymbolAddress((void**)&ph1h, h1_h); cudaGetSymbolAddress((void**)&ph1l, h1_l);
    cudaGetSymbolAddress((void**)&pqh, qkvp_h); cudaGetSymbolAddress((void**)&pql, qkvp_l);
    __nv_bfloat16 *pwqh, *pwql, *pwph, *pwpl, *pw1h, *pw1l, *pw2h, *pw2l, *plmh, *plml;
    cudaGetSymbolAddress((void**)&pwqh, wqkv_h); cudaGetSymbolAddress((void**)&pwql, wqkv_l);
    cudaGetSymbolAddress((void**)&pwph, wpr_h);  cudaGetSymbolAddress((void**)&pwpl, wpr_l);
    cudaGetSymbolAddress((void**)&pw1h, w1b_h);  cudaGetSymbolAddress((void**)&pw1l, w1b_l);
    cudaGetSymbolAddress((void**)&pw2h, w2b_h);  cudaGetSymbolAddress((void**)&pw2l, w2b_l);
    cudaGetSymbolAddress((void**)&plmh, lmw_h);  cudaGetSymbolAddress((void**)&plml, lmw_l);

    conv_qkv<<<1024, 256>>>(wq, wk, wv);
    split_flat<<<512, 256>>>((const float4*)wproj, (uint2*)pwph, (uint2*)pwpl,
                             (unsigned)(Ll * Dd * Dd / 4));
    split_flat<<<1024, 256>>>((const float4*)w1, (uint2*)pw1h, (uint2*)pw1l,
                              (unsigned)(Ll * Dd * DFF / 4));
    split_flat<<<1024, 256>>>((const float4*)w2, (uint2*)pw2h, (uint2*)pw2l,
                              (unsigned)(Ll * DFF * Dd / 4));
    conv_lm<<<2048, 256>>>(lm_w);

    embed_kernel<<<Mm, 256>>>(idx, tok_emb, pos_emb);

    for (int l = 0; l < Ll; l++) {
        // QKV -> bf16 hi/lo pairs
        gemm_bf3<<<dim3(Mm / TM, NQKV / TN), 256, GEMM_SMEM>>>(
            pxh, pxl, Dd,
            pwqh + (size_t)l * Dd * NQKV, pwql + (size_t)l * Dd * NQKV, NQKV,
            nullptr, nullptr, pqh, pql, NQKV, NQKV, Dd, 0, 1);
        // fused flash attention -> o hi/lo
        flash_kernel<<<dim3(Tt / FBM, Bq * Hh), 128, FLASH_SMEM>>>();
        // proj -> fp32 tmp
        gemm_bf3<<<dim3(Mm / TM, Dd / TN), 256, GEMM_SMEM>>>(
            poh, pol, Dd,
            pwph + (size_t)l * Dd * Dd, pwpl + (size_t)l * Dd * Dd, Dd,
            bproj + (size_t)l * Dd, p_tmp, nullptr, nullptr, Dd, Dd, Dd, 0, 0);
        addln_kernel<<<Mm / 8, 256>>>(p_tmp, ln1_g + (size_t)l * Dd, ln1_b + (size_t)l * Dd);
        // fc1 -> bf16 pair + relu
        gemm_bf3<<<dim3(Mm / TM, DFF / TN), 256, GEMM_SMEM>>>(
            pxh, pxl, Dd,
            pw1h + (size_t)l * Dd * DFF, pw1l + (size_t)l * Dd * DFF, DFF,
            b1 + (size_t)l * DFF, nullptr, ph1h, ph1l, DFF, DFF, Dd, 1, 1);
        // fc2 -> fp32 tmp
        gemm_bf3<<<dim3(Mm / TM, Dd / TN), 256, GEMM_SMEM>>>(
            ph1h, ph1l, DFF,
            pw2h + (size_t)l * DFF * Dd, pw2l + (size_t)l * DFF * Dd, Dd,
            b2 + (size_t)l * Dd, p_tmp, nullptr, nullptr, Dd, Dd, DFF, 0, 0);
        addln_kernel<<<Mm / 8, 256>>>(p_tmp, ln2_g + (size_t)l * Dd, ln2_b + (size_t)l * Dd);
    }

    gemm_bf3<<<dim3(Mm / TM, VP / TN), 256, GEMM_SMEM>>>(
        pxh, pxl, Dd, plmh, plml, VP,
        lm_b, out, nullptr, nullptr, Vv, Vv, Dd, 0, 0);
}

// round 8
// speedup vs baseline: 4.1797x; 1.0917x over previous
#include <cuda_runtime.h>
#include <cuda_bf16.h>
#include <cuda_fp16.h>
#include <cstdint>
#include <math.h>
#include <stddef.h>

// Problem constants
#define Bq 2
#define Tt 1024
#define Dd 768
#define Hh 12
#define Ll 6
#define Vv 50257
#define VP 50304
#define HS 64
#define Mm (Bq*Tt)
#define DFF (4*Dd)
#define NQKV (3*Dd)

// GEMM tiling
#define TM 128
#define TN 128
#define BK 32
#define SA_STRIDE 40
#define SB_STRIDE 136
#define OFF_AH 0
#define OFF_AL 10240
#define OFF_BH 20480
#define OFF_BL 29184
#define STAGE_BYTES 37888
#define GEMM_SMEM (2*STAGE_BYTES)

// Flash attention tiling (FBM=64, 128 threads, 4 warps)
#define FBM 64
#define FBN 64
#define FST_KH 0
#define FST_KL 9216
#define FST_VH 18432
#define FST_VL 27648
#define FSTAGE 36864
#define FLASH_SMEM (2*FSTAGE)

// ---------------- scratch --------------------------------------------------
__device__ float g_x  [Mm*Dd];
__device__ float g_tmp[Mm*Dd];

__device__ __nv_bfloat16 x_h [Mm*Dd],  x_l [Mm*Dd];
__device__ __half        x16 [Mm*Dd];
__device__ __nv_bfloat16 o_h [Mm*Dd],  o_l [Mm*Dd];
__device__ __nv_bfloat16 h1_h[(size_t)Mm*DFF], h1_l[(size_t)Mm*DFF];
__device__ __nv_bfloat16 qkvp_h[(size_t)Mm*NQKV], qkvp_l[(size_t)Mm*NQKV];

__device__ __nv_bfloat16 wqkv_h[(size_t)Ll*Dd*NQKV], wqkv_l[(size_t)Ll*Dd*NQKV];
__device__ __nv_bfloat16 wpr_h [(size_t)Ll*Dd*Dd],   wpr_l [(size_t)Ll*Dd*Dd];
__device__ __nv_bfloat16 w1b_h [(size_t)Ll*Dd*DFF],  w1b_l [(size_t)Ll*Dd*DFF];
__device__ __nv_bfloat16 w2b_h [(size_t)Ll*DFF*Dd],  w2b_l [(size_t)Ll*DFF*Dd];
__device__ __half        lmw16_h[(size_t)Dd*VP],     lmw16_l[(size_t)Dd*VP];

// ---------------- helpers --------------------------------------------------
__device__ __forceinline__ uint32_t s2u(const void* p) {
    uint32_t a;
    asm("{ .reg .u64 t; cvta.to.shared.u64 t, %1; cvt.u32.u64 %0, t; }" : "=r"(a) : "l"(p));
    return a;
}
__device__ __forceinline__ void cpa16(uint32_t dst, const void* src) {
    asm volatile("cp.async.cg.shared.global [%0], [%1], 16;" :: "r"(dst), "l"(src));
}
__device__ __forceinline__ void ldmx4(uint32_t* r, uint32_t addr) {
    asm volatile("ldmatrix.sync.aligned.m8n8.x4.shared.b16 {%0,%1,%2,%3},[%4];"
                 : "=r"(r[0]), "=r"(r[1]), "=r"(r[2]), "=r"(r[3]) : "r"(addr));
}
__device__ __forceinline__ void ldmx4t(uint32_t* r, uint32_t addr) {
    asm volatile("ldmatrix.sync.aligned.m8n8.x4.trans.shared.b16 {%0,%1,%2,%3},[%4];"
                 : "=r"(r[0]), "=r"(r[1]), "=r"(r[2]), "=r"(r[3]) : "r"(addr));
}
__device__ __forceinline__ void mma_bf16(float* c, const uint32_t* a,
                                         uint32_t b0, uint32_t b1) {
    asm volatile(
        "mma.sync.aligned.m16n8k16.row.col.f32.bf16.bf16.f32 "
        "{%0,%1,%2,%3},{%4,%5,%6,%7},{%8,%9},{%0,%1,%2,%3};"
        : "+f"(c[0]), "+f"(c[1]), "+f"(c[2]), "+f"(c[3])
        : "r"(a[0]), "r"(a[1]), "r"(a[2]), "r"(a[3]), "r"(b0), "r"(b1));
}
__device__ __forceinline__ void mma_f16(float* c, const uint32_t* a,
                                        uint32_t b0, uint32_t b1) {
    asm volatile(
        "mma.sync.aligned.m16n8k16.row.col.f32.f16.f16.f32 "
        "{%0,%1,%2,%3},{%4,%5,%6,%7},{%8,%9},{%0,%1,%2,%3};"
        : "+f"(c[0]), "+f"(c[1]), "+f"(c[2]), "+f"(c[3])
        : "r"(a[0]), "r"(a[1]), "r"(a[2]), "r"(a[3]), "r"(b0), "r"(b1));
}
__device__ __forceinline__ void splitv(float v, __nv_bfloat16& h, __nv_bfloat16& l) {
    h = __float2bfloat16_rn(v);
    l = __float2bfloat16_rn(v - __bfloat162float(h));
}
__device__ __forceinline__ uint32_t pk(__nv_bfloat16 a, __nv_bfloat16 b) {
    return ((uint32_t)__bfloat16_as_ushort(b) << 16) | __bfloat16_as_ushort(a);
}
__device__ __forceinline__ uint32_t pkh(__half a, __half b) {
    return ((uint32_t)__half_as_ushort(b) << 16) | __half_as_ushort(a);
}
__device__ __forceinline__ void split4(float4 v, uint2& h, uint2& l) {
    __nv_bfloat16 h0, h1, h2, h3, l0, l1, l2, l3;
    splitv(v.x, h0, l0); splitv(v.y, h1, l1);
    splitv(v.z, h2, l2); splitv(v.w, h3, l3);
    h = make_uint2(pk(h0, h1), pk(h2, h3));
    l = make_uint2(pk(l0, l1), pk(l2, l3));
}
__device__ __forceinline__ void split4h(float4 v, uint2& h, uint2& l) {
    __half h0 = __float2half_rn(v.x), h1 = __float2half_rn(v.y);
    __half h2 = __float2half_rn(v.z), h3 = __float2half_rn(v.w);
    __half l0 = __float2half_rn(v.x - __half2float(h0));
    __half l1 = __float2half_rn(v.y - __half2float(h1));
    __half l2 = __float2half_rn(v.z - __half2float(h2));
    __half l3 = __float2half_rn(v.w - __half2float(h3));
    h = make_uint2(pkh(h0, h1), pkh(h2, h3));
    l = make_uint2(pkh(l0, l1), pkh(l2, l3));
}

// ---------------- weight conversion ----------------------------------------
__global__ void split_flat(const float4* __restrict__ src,
                           uint2* __restrict__ h,
                           uint2* __restrict__ l, unsigned n4) {
    unsigned stride = gridDim.x * blockDim.x;
    for (unsigned i = blockIdx.x * blockDim.x + threadIdx.x; i < n4; i += 2 * stride) {
        unsigned j = i + stride;
        float4 a = src[i];
        float4 b;
        bool has2 = (j < n4);
        if (has2) b = src[j];
        uint2 ha, la;
        split4(a, ha, la);
        h[i] = ha; l[i] = la;
        if (has2) {
            uint2 hb, lb;
            split4(b, hb, lb);
            h[j] = hb; l[j] = lb;
        }
    }
}

__device__ __forceinline__ void qkv_one(const float* __restrict__ wq,
                                        const float* __restrict__ wk,
                                        const float* __restrict__ wv,
                                        unsigned i4) {
    unsigned e = i4 * 4u;
    unsigned l = e / (unsigned)(Dd * NQKV);
    unsigned r = e - l * (unsigned)(Dd * NQKV);
    unsigned k = r / (unsigned)NQKV;
    unsigned n = r - k * (unsigned)NQKV;
    unsigned wsel = n / (unsigned)Dd;
    unsigned r2 = n - wsel * (unsigned)Dd;
    unsigned hh = r2 >> 6, s = r2 & 63;
    const float* base = (wsel == 0) ? wq : ((wsel == 1) ? wk : wv);
    float4 v = *(const float4*)(base + ((size_t)(l * Hh + hh) * Dd + k) * HS + s);
    uint2 hp, lp;
    split4(v, hp, lp);
    ((uint2*)wqkv_h)[i4] = hp;
    ((uint2*)wqkv_l)[i4] = lp;
}
__global__ void conv_qkv(const float* __restrict__ wq,
                         const float* __restrict__ wk,
                         const float* __restrict__ wv) {
    const unsigned total4 = (unsigned)Ll * Dd * NQKV / 4u;
    unsigned stride = gridDim.x * blockDim.x;
    for (unsigned i = blockIdx.x * blockDim.x + threadIdx.x; i < total4; i += 2 * stride) {
        qkv_one(wq, wk, wv, i);
        if (i + stride < total4) qkv_one(wq, wk, wv, i + stride);
    }
}

__device__ __forceinline__ void lm_one(const float* __restrict__ lm_w, unsigned i4) {
    unsigned e = i4 * 4u;
    unsigned k = e / (unsigned)VP;
    unsigned n = e - k * (unsigned)VP;
    const float* row = lm_w + (size_t)k * Vv;
    float4 v;
    v.x = (n     < Vv) ? row[n]     : 0.f;
    v.y = (n + 1 < Vv) ? row[n + 1] : 0.f;
    v.z = (n + 2 < Vv) ? row[n + 2] : 0.f;
    v.w = (n + 3 < Vv) ? row[n + 3] : 0.f;
    uint2 hp, lp;
    split4h(v, hp, lp);
    ((uint2*)lmw16_h)[i4] = hp;
    ((uint2*)lmw16_l)[i4] = lp;
}
__global__ void conv_lm(const float* __restrict__ lm_w) {
    const unsigned total4 = (unsigned)Dd * VP / 4u;
    unsigned stride = gridDim.x * blockDim.x;
    for (unsigned i = blockIdx.x * blockDim.x + threadIdx.x; i < total4; i += 2 * stride) {
        lm_one(lm_w, i);
        if (i + stride < total4) lm_one(lm_w, i + stride);
    }
}

// x (fp32) -> fp16 copy for lm_head A operand
__global__ void conv_x16() {
    unsigned i4 = blockIdx.x * blockDim.x + threadIdx.x;   // Mm*Dd/4 = 393216
    if (i4 < (unsigned)(Mm * Dd / 4)) {
        float4 v = ((const float4*)g_x)[i4];
        uint2 h;
        h.x = pkh(__float2half_rn(v.x), __float2half_rn(v.y));
        h.y = pkh(__float2half_rn(v.z), __float2half_rn(v.w));
        ((uint2*)x16)[i4] = h;
    }
}

// ---------------- templated tensor-core GEMM (cp.async double-buffered) ----
// MODE 0: bf16 3-pass (AhBh + AhBl + AlBh). MODE 1: fp16 2-pass (AhBh + AhBl),
// A low term not loaded at all.
template<int MODE>
__global__ __launch_bounds__(256, 2) void gemm_mp(
    const __nv_bfloat16* __restrict__ Ah_g, const __nv_bfloat16* __restrict__ Al_g,
    int lda,
    const __nv_bfloat16* __restrict__ Bh_g, const __nv_bfloat16* __restrict__ Bl_g,
    int ldb,
    const float* __restrict__ bias,
    float* __restrict__ Cf,
    __nv_bfloat16* __restrict__ Ch, __nv_bfloat16* __restrict__ Cl,
    int ldc, int N, int K, int relu, int outmode)
{
    extern __shared__ char smem[];
    const uint32_t sb = s2u(smem);
    const int tid = threadIdx.x;
    const int wid = tid >> 5, lane = tid & 31;
    const int m0 = blockIdx.x * TM;
    const int n0 = blockIdx.y * TN;
    const int mw = (wid & 3) * 32;
    const int nw = (wid >> 2) * 64;

    float acc[2][8][4];
    #pragma unroll
    for (int a = 0; a < 2; a++)
        #pragma unroll
        for (int b = 0; b < 8; b++)
            #pragma unroll
            for (int c = 0; c < 4; c++) acc[a][b][c] = 0.f;

    auto load_stage = [&](int kc, int st) {
        uint32_t base = sb + st * STAGE_BYTES;
        #pragma unroll
        for (int i = 0; i < 2; i++) {
            int c = tid + i * 256;
            int row = c >> 2, q = c & 3;
            uint32_t d = base + OFF_AH + row * 80 + q * 16;
            cpa16(d, Ah_g + (size_t)(m0 + row) * lda + kc + q * 8);
            if (MODE == 0)
                cpa16(d + (OFF_AL - OFF_AH), Al_g + (size_t)(m0 + row) * lda + kc + q * 8);
        }
        #pragma unroll
        for (int i = 0; i < 2; i++) {
            int c = tid + i * 256;
            int row = c >> 4, q = c & 15;
            uint32_t d = base + OFF_BH + row * 272 + q * 16;
            cpa16(d, Bh_g + (size_t)(kc + row) * ldb + n0 + q * 8);
            cpa16(d + (OFF_BL - OFF_BH), Bl_g + (size_t)(kc + row) * ldb + n0 + q * 8);
        }
        asm volatile("cp.async.commit_group;" ::: "memory");
    };

    const int niter = K / BK;
    load_stage(0, 0);

    for (int it = 0; it < niter; it++) {
        if (it + 1 < niter) {
            load_stage((it + 1) * BK, (it + 1) & 1);
            asm volatile("cp.async.wait_group 1;" ::: "memory");
        } else {
            asm volatile("cp.async.wait_group 0;" ::: "memory");
        }
        __syncthreads();

        const uint32_t sbase = sb + (it & 1) * STAGE_BYTES;
        #pragma unroll
        for (int kk = 0; kk < BK; kk += 16) {
            uint32_t ah[2][4], al[2][4];
            int arow = mw + (lane & 15);
            int acol = kk + (lane >> 4) * 8;
            #pragma unroll
            for (int mi = 0; mi < 2; mi++) {
                uint32_t off = (uint32_t)(arow + mi * 16) * (SA_STRIDE * 2) + acol * 2;
                ldmx4(ah[mi], sbase + OFF_AH + off);
                if (MODE == 0) ldmx4(al[mi], sbase + OFF_AL + off);
            }
            int brow = kk + (lane & 15);
            int bcol = nw + (lane >> 4) * 8;
            #pragma unroll
            for (int ni = 0; ni < 4; ni++) {
                uint32_t off = (uint32_t)brow * (SB_STRIDE * 2) + (bcol + ni * 16) * 2;
                uint32_t bh[4], bl[4];
                ldmx4t(bh, sbase + OFF_BH + off);
                ldmx4t(bl, sbase + OFF_BL + off);
                #pragma unroll
                for (int mi = 0; mi < 2; mi++) {
                    if (MODE == 0) {
                        mma_bf16(acc[mi][2 * ni],     ah[mi], bh[0], bh[1]);
                        mma_bf16(acc[mi][2 * ni],     ah[mi], bl[0], bl[1]);
                        mma_bf16(acc[mi][2 * ni],     al[mi], bh[0], bh[1]);
                        mma_bf16(acc[mi][2 * ni + 1], ah[mi], bh[2], bh[3]);
                        mma_bf16(acc[mi][2 * ni + 1], ah[mi], bl[2], bl[3]);
                        mma_bf16(acc[mi][2 * ni + 1], al[mi], bh[2], bh[3]);
                    } else {
                        mma_f16(acc[mi][2 * ni],     ah[mi], bh[0], bh[1]);
                        mma_f16(acc[mi][2 * ni],     ah[mi], bl[0], bl[1]);
                        mma_f16(acc[mi][2 * ni + 1], ah[mi], bh[2], bh[3]);
                        mma_f16(acc[mi][2 * ni + 1], ah[mi], bl[2], bl[3]);
                    }
                }
            }
        }
        __syncthreads();
    }

    float* sC = (float*)smem;
    const int r0 = mw + (lane >> 2);
    const int c0 = 2 * (lane & 3);
    #pragma unroll 1
    for (int hf = 0; hf < 2; hf++) {
        if ((wid >> 2) == hf) {
            #pragma unroll
            for (int mi = 0; mi < 2; mi++)
                #pragma unroll
                for (int ni = 0; ni < 8; ni++) {
                    int rr = (r0 + mi * 16) * 68 + ni * 8 + c0;
                    sC[rr]              = acc[mi][ni][0];
                    sC[rr + 1]          = acc[mi][ni][1];
                    sC[rr + 8 * 68]     = acc[mi][ni][2];
                    sC[rr + 8 * 68 + 1] = acc[mi][ni][3];
                }
        }
        __syncthreads();
        #pragma unroll 4
        for (int it = 0; it < 32; it++) {
            int idx = tid + it * 256;
            int r = idx >> 6, c = idx & 63;
            int col = n0 + hf * 64 + c;
            if (col < N) {
                float v = sC[r * 68 + c];
                if (bias) v += bias[col];
                if (relu) v = fmaxf(v, 0.f);
                if (outmode == 0) {
                    Cf[(size_t)(m0 + r) * ldc + col] = v;
                } else {
                    __nv_bfloat16 hh, ll;
                    splitv(v, hh, ll);
                    Ch[(size_t)(m0 + r) * ldc + col] = hh;
                    Cl[(size_t)(m0 + r) * ldc + col] = ll;
                }
            }
        }
        __syncthreads();
    }
}

// ---------------- flash attention (bf16x3, causal, online softmax) ---------
__global__ __launch_bounds__(128) void flash_kernel() {
    extern __shared__ char smem[];
    const uint32_t sb = s2u(smem);
    const int tid = threadIdx.x, wid = tid >> 5, lane = tid & 31;
    const int bh = blockIdx.y;
    const int b = bh / Hh, h = bh % Hh;
    const int t0 = (int)(gridDim.x - 1 - blockIdx.x) * FBM;
    const int mw = wid * 16;

    const size_t rowbase = (size_t)(b * Tt) * NQKV + h * HS;

    #pragma unroll
    for (int i = 0; i < 4; i++) {
        int c = tid + i * 128;
        int row = c >> 3, q = c & 7;
        size_t g = rowbase + (size_t)(t0 + row) * NQKV + q * 8;
        cpa16(sb + row * 144 + q * 16, qkvp_h + g);
        cpa16(sb + 9216 + row * 144 + q * 16, qkvp_l + g);
    }
    asm volatile("cp.async.commit_group;" ::: "memory");
    asm volatile("cp.async.wait_group 0;" ::: "memory");
    __syncthreads();

    uint32_t qfh[4][4], qfl[4][4];
    {
        int arow = mw + (lane & 15);
        #pragma unroll
        for (int kk = 0; kk < 4; kk++) {
            int acol = kk * 16 + (lane >> 4) * 8;
            uint32_t off = (uint32_t)arow * 144 + acol * 2;
            ldmx4(qfh[kk], sb + off);
            ldmx4(qfl[kk], sb + 9216 + off);
        }
    }
    __syncthreads();

    auto kv_issue = [&](int u0, int st) {
        uint32_t base = sb + st * FSTAGE;
        #pragma unroll
        for (int i = 0; i < 4; i++) {
            int c = tid + i * 128;
            int row = c >> 3, q = c & 7;
            size_t g = rowbase + (size_t)(u0 + row) * NQKV + q * 8;
            uint32_t d = base + row * 144 + q * 16;
            cpa16(d + FST_KH, qkvp_h + g + Dd);
            cpa16(d + FST_KL, qkvp_l + g + Dd);
            cpa16(d + FST_VH, qkvp_h + g + 2 * Dd);
            cpa16(d + FST_VL, qkvp_l + g + 2 * Dd);
        }
        asm volatile("cp.async.commit_group;" ::: "memory");
    };

    float o[8][4];
    #pragma unroll
    for (int i = 0; i < 8; i++)
        #pragma unroll
        for (int j = 0; j < 4; j++) o[i][j] = 0.f;
    float mA = -1e30f, mB = -1e30f, lA = 0.f, lB = 0.f;

    const int nt = t0 / FBN + 1;
    kv_issue(0, 1);

    for (int it = 0; it < nt; it++) {
        const int u0 = it * FBN;
        if (it + 1 < nt) {
            kv_issue((it + 1) * FBN, it & 1);
            asm volatile("cp.async.wait_group 1;" ::: "memory");
        } else {
            asm volatile("cp.async.wait_group 0;" ::: "memory");
        }
        __syncthreads();
        const uint32_t kb = sb + ((it + 1) & 1) * FSTAGE;

        float s[8][4];
        #pragma unroll
        for (int i = 0; i < 8; i++)
            #pragma unroll
            for (int j = 0; j < 4; j++) s[i][j] = 0.f;

        const int bn = ((lane >> 4) << 3) + (lane & 7);
        const int bk = ((lane >> 3) & 1) * 8;
        #pragma unroll
        for (int kk = 0; kk < 4; kk++) {
            #pragma unroll
            for (int j = 0; j < 4; j++) {
                uint32_t addr = kb + (uint32_t)(j * 16 + bn) * 144 + (kk * 16 + bk) * 2;
                uint32_t kh4[4], kl4[4];
                ldmx4(kh4, addr + FST_KH);
                ldmx4(kl4, addr + FST_KL);
                mma_bf16(s[2 * j],     qfh[kk], kh4[0], kh4[1]);
                mma_bf16(s[2 * j],     qfh[kk], kl4[0], kl4[1]);
                mma_bf16(s[2 * j],     qfl[kk], kh4[0], kh4[1]);
                mma_bf16(s[2 * j + 1], qfh[kk], kh4[2], kh4[3]);
                mma_bf16(s[2 * j + 1], qfh[kk], kl4[2], kl4[3]);
                mma_bf16(s[2 * j + 1], qfl[kk], kh4[2], kh4[3]);
            }
        }

        const int rA = lane >> 2;
        const int tA = t0 + mw + rA, tB = tA + 8;
        #pragma unroll
        for (int nb = 0; nb < 8; nb++)
            #pragma unroll
            for (int j = 0; j < 4; j++) s[nb][j] *= 0.125f;
        if (u0 + FBN - 1 > t0 + mw) {
            #pragma unroll
            for (int nb = 0; nb < 8; nb++) {
                int u_lo = u0 + nb * 8 + (lane & 3) * 2;
                if (u_lo     > tA) s[nb][0] = -1e30f;
                if (u_lo + 1 > tA) s[nb][1] = -1e30f;
                if (u_lo     > tB) s[nb][2] = -1e30f;
                if (u_lo + 1 > tB) s[nb][3] = -1e30f;
            }
        }

        float rmA = -1e30f, rmB = -1e30f;
        #pragma unroll
        for (int nb = 0; nb < 8; nb++) {
            rmA = fmaxf(rmA, fmaxf(s[nb][0], s[nb][1]));
            rmB = fmaxf(rmB, fmaxf(s[nb][2], s[nb][3]));
        }
        rmA = fmaxf(rmA, __shfl_xor_sync(0xffffffffu, rmA, 1));
        rmA = fmaxf(rmA, __shfl_xor_sync(0xffffffffu, rmA, 2));
        rmB = fmaxf(rmB, __shfl_xor_sync(0xffffffffu, rmB, 1));
        rmB = fmaxf(rmB, __shfl_xor_sync(0xffffffffu, rmB, 2));
        float mAn = fmaxf(mA, rmA), mBn = fmaxf(mB, rmB);
        float scA = __expf(mA - mAn), scB = __expf(mB - mBn);
        mA = mAn; mB = mBn;

        float rsA = 0.f, rsB = 0.f;
        #pragma unroll
        for (int nb = 0; nb < 8; nb++) {
            s[nb][0] = __expf(s[nb][0] - mA); rsA += s[nb][0];
            s[nb][1] = __expf(s[nb][1] - mA); rsA += s[nb][1];
            s[nb][2] = __expf(s[nb][2] - mB); rsB += s[nb][2];
            s[nb][3] = __expf(s[nb][3] - mB); rsB += s[nb][3];
        }
        rsA += __shfl_xor_sync(0xffffffffu, rsA, 1);
        rsA += __shfl_xor_sync(0xffffffffu, rsA, 2);
        rsB += __shfl_xor_sync(0xffffffffu, rsB, 1);
        rsB += __shfl_xor_sync(0xffffffffu, rsB, 2);
        lA = lA * scA + rsA;
        lB = lB * scB + rsB;
        #pragma unroll
        for (int nb = 0; nb < 8; nb++) {
            o[nb][0] *= scA; o[nb][1] *= scA;
            o[nb][2] *= scB; o[nb][3] *= scB;
        }

        #pragma unroll
        for (int g = 0; g < 4; g++) {
            uint32_t pha[4], pla[4];
            {
                __nv_bfloat16 h0, h1, l0, l1;
                splitv(s[2 * g][0], h0, l0); splitv(s[2 * g][1], h1, l1);
                pha[0] = pk(h0, h1); pla[0] = pk(l0, l1);
                splitv(s[2 * g][2], h0, l0); splitv(s[2 * g][3], h1, l1);
                pha[1] = pk(h0, h1); pla[1] = pk(l0, l1);
                splitv(s[2 * g + 1][0], h0, l0); splitv(s[2 * g + 1][1], h1, l1);
                pha[2] = pk(h0, h1); pla[2] = pk(l0, l1);
                splitv(s[2 * g + 1][2], h0, l0); splitv(s[2 * g + 1][3], h1, l1);
                pha[3] = pk(h0, h1); pla[3] = pk(l0, l1);
            }
            const int vrow = g * 16 + (lane & 15);
            #pragma unroll
            for (int j = 0; j < 4; j++) {
                uint32_t addr = kb + (uint32_t)vrow * 144 +
                                (uint32_t)(j * 16 + (lane >> 4) * 8) * 2;
                uint32_t vh4[4], vl4[4];
                ldmx4t(vh4, addr + FST_VH);
                ldmx4t(vl4, addr + FST_VL);
                mma_bf16(o[2 * j],     pha, vh4[0], vh4[1]);
                mma_bf16(o[2 * j],     pha, vl4[0], vl4[1]);
                mma_bf16(o[2 * j],     pla, vh4[0], vh4[1]);
                mma_bf16(o[2 * j + 1], pha, vh4[2], vh4[3]);
                mma_bf16(o[2 * j + 1], pha, vl4[2], vl4[3]);
                mma_bf16(o[2 * j + 1], pla, vh4[2], vh4[3]);
            }
        }
        __syncthreads();
    }

    const float invA = 1.f / lA, invB = 1.f / lB;
    const int rA = lane >> 2;
    const int tA = t0 + mw + rA, tB = tA + 8;
    const int cbase = h * HS + (lane & 3) * 2;
    size_t baseA = (size_t)(b * Tt + tA) * Dd + cbase;
    size_t baseB = (size_t)(b * Tt + tB) * Dd + cbase;
    #pragma unroll
    for (int nb = 0; nb < 8; nb++) {
        splitv(o[nb][0] * invA, o_h[baseA + nb * 8],     o_l[baseA + nb * 8]);
        splitv(o[nb][1] * invA, o_h[baseA + nb * 8 + 1], o_l[baseA + nb * 8 + 1]);
        splitv(o[nb][2] * invB, o_h[baseB + nb * 8],     o_l[baseB + nb * 8]);
        splitv(o[nb][3] * invB, o_h[baseB + nb * 8 + 1], o_l[baseB + nb * 8 + 1]);
    }
}

// ---------------- embedding -------------------------------------------------
__global__ void embed_kernel(const int* __restrict__ idx,
                             const float* __restrict__ tok_emb,
                             const float* __restrict__ pos_emb) {
    int m = blockIdx.x;
    int t = m % Tt;
    int tok = idx[m];
    const float* te = tok_emb + (size_t)tok * Dd;
    const float* pe = pos_emb + (size_t)t * Dd;
    float* x = g_x + (size_t)m * Dd;
    for (int c = threadIdx.x; c < Dd; c += blockDim.x) {
        float v = te[c] + pe[c];
        x[c] = v;
        splitv(v, x_h[(size_t)m * Dd + c], x_l[(size_t)m * Dd + c]);
    }
}

// ---------------- fused residual add + LayerNorm (warp per row) ------------
__global__ void addln_kernel(const float* __restrict__ add,
                             const float* __restrict__ gamma,
                             const float* __restrict__ beta) {
    int row = blockIdx.x * (blockDim.x >> 5) + (threadIdx.x >> 5);
    int lane = threadIdx.x & 31;
    float* x = g_x + (size_t)row * Dd;
    const float* a = add + (size_t)row * Dd;

    float v[24];
    float s = 0.f;
    #pragma unroll
    for (int i = 0; i < 24; i++) {
        int c = lane + i * 32;
        v[i] = x[c] + a[c];
        s += v[i];
    }
    #pragma unroll
    for (int o = 16; o > 0; o >>= 1) s += __shfl_xor_sync(0xffffffffu, s, o);
    float mean = s * (1.f / Dd);

    float q = 0.f;
    #pragma unroll
    for (int i = 0; i < 24; i++) {
        float d = v[i] - mean;
        q += d * d;
    }
    #pragma unroll
    for (int o = 16; o > 0; o >>= 1) q += __shfl_xor_sync(0xffffffffu, q, o);
    float rstd = rsqrtf(q * (1.f / Dd) + 1e-5f);

    #pragma unroll
    for (int i = 0; i < 24; i++) {
        int c = lane + i * 32;
        float ov = (v[i] - mean) * rstd * gamma[c] + beta[c];
        x[c] = ov;
        splitv(ov, x_h[(size_t)row * Dd + c], x_l[(size_t)row * Dd + c]);
    }
}

// ---------------- host orchestration ----------------------------------------
extern "C" void kernel_launch(void* const* d_in, const int* in_sizes, int n_in,
                              void* d_out, int out_size) {
    const int*   idx     = (const int*)  d_in[0];
    const float* tok_emb = (const float*)d_in[1];
    const float* pos_emb = (const float*)d_in[2];
    const float* wq      = (const float*)d_in[3];
    const float* wk      = (const float*)d_in[4];
    const float* wv      = (const float*)d_in[5];
    const float* wproj   = (const float*)d_in[6];
    const float* bproj   = (const float*)d_in[7];
    const float* w1      = (const float*)d_in[8];
    const float* b1      = (const float*)d_in[9];
    const float* w2      = (const float*)d_in[10];
    const float* b2      = (const float*)d_in[11];
    const float* ln1_g   = (const float*)d_in[12];
    const float* ln1_b   = (const float*)d_in[13];
    const float* ln2_g   = (const float*)d_in[14];
    const float* ln2_b   = (const float*)d_in[15];
    const float* lm_w    = (const float*)d_in[16];
    const float* lm_b    = (const float*)d_in[17];
    float* out = (float*)d_out;

    cudaFuncSetAttribute(gemm_mp<0>, cudaFuncAttributeMaxDynamicSharedMemorySize, GEMM_SMEM);
    cudaFuncSetAttribute(gemm_mp<1>, cudaFuncAttributeMaxDynamicSharedMemorySize, GEMM_SMEM);
    cudaFuncSetAttribute(flash_kernel, cudaFuncAttributeMaxDynamicSharedMemorySize, FLASH_SMEM);

    float *p_x, *p_tmp;
    cudaGetSymbolAddress((void**)&p_x,   g_x);
    cudaGetSymbolAddress((void**)&p_tmp, g_tmp);
    __nv_bfloat16 *pxh, *pxl, *poh, *pol, *ph1h, *ph1l, *pqh, *pql;
    cudaGetSymbolAddress((void**)&pxh, x_h);   cudaGetSymbolAddress((void**)&pxl, x_l);
    cudaGetSymbolAddress((void**)&poh, o_h);   cudaGetSymbolAddress((void**)&pol, o_l);
    cudaGetSymbolAddress((void**)&ph1h, h1_h); cudaGetSymbolAddress((void**)&ph1l, h1_l);
    cudaGetSymbolAddress((void**)&pqh, qkvp_h); cudaGetSymbolAddress((void**)&pql, qkvp_l);
    __nv_bfloat16 *pwqh, *pwql, *pwph, *pwpl, *pw1h, *pw1l, *pw2h, *pw2l;
    cudaGetSymbolAddress((void**)&pwqh, wqkv_h); cudaGetSymbolAddress((void**)&pwql, wqkv_l);
    cudaGetSymbolAddress((void**)&pwph, wpr_h);  cudaGetSymbolAddress((void**)&pwpl, wpr_l);
    cudaGetSymbolAddress((void**)&pw1h, w1b_h);  cudaGetSymbolAddress((void**)&pw1l, w1b_l);
    cudaGetSymbolAddress((void**)&pw2h, w2b_h);  cudaGetSymbolAddress((void**)&pw2l, w2b_l);
    __half *plmh, *plml, *px16;
    cudaGetSymbolAddress((void**)&plmh, lmw16_h);
    cudaGetSymbolAddress((void**)&plml, lmw16_l);
    cudaGetSymbolAddress((void**)&px16, x16);

    conv_qkv<<<1024, 256>>>(wq, wk, wv);
    split_flat<<<512, 256>>>((const float4*)wproj, (uint2*)pwph, (uint2*)pwpl,
                             (unsigned)(Ll * Dd * Dd / 4));
    split_flat<<<1024, 256>>>((const float4*)w1, (uint2*)pw1h, (uint2*)pw1l,
                              (unsigned)(Ll * Dd * DFF / 4));
    split_flat<<<1024, 256>>>((const float4*)w2, (uint2*)pw2h, (uint2*)pw2l,
                              (unsigned)(Ll * DFF * Dd / 4));
    conv_lm<<<2048, 256>>>(lm_w);

    embed_kernel<<<Mm, 256>>>(idx, tok_emb, pos_emb);

    for (int l = 0; l < Ll; l++) {
        gemm_mp<0><<<dim3(Mm / TM, NQKV / TN), 256, GEMM_SMEM>>>(
            pxh, pxl, Dd,
            pwqh + (size_t)l * Dd * NQKV, pwql + (size_t)l * Dd * NQKV, NQKV,
            nullptr, nullptr, pqh, pql, NQKV, NQKV, Dd, 0, 1);
        flash_kernel<<<dim3(Tt / FBM, Bq * Hh), 128, FLASH_SMEM>>>();
        gemm_mp<0><<<dim3(Mm / TM, Dd / TN), 256, GEMM_SMEM>>>(
            poh, pol, Dd,
            pwph + (size_t)l * Dd * Dd, pwpl + (size_t)l * Dd * Dd, Dd,
            bproj + (size_t)l * Dd, p_tmp, nullptr, nullptr, Dd, Dd, Dd, 0, 0);
        addln_kernel<<<Mm / 8, 256>>>(p_tmp, ln1_g + (size_t)l * Dd, ln1_b + (size_t)l * Dd);
        gemm_mp<0><<<dim3(Mm / TM, DFF / TN), 256, GEMM_SMEM>>>(
            pxh, pxl, Dd,
            pw1h + (size_t)l * Dd * DFF, pw1l + (size_t)l * Dd * DFF, DFF,
            b1 + (size_t)l * DFF, nullptr, ph1h, ph1l, DFF, DFF, Dd, 1, 1);
        gemm_mp<0><<<dim3(Mm / TM, Dd / TN), 256, GEMM_SMEM>>>(
            ph1h, ph1l, DFF,
            pw2h + (size_t)l * DFF * Dd, pw2l + (size_t)l * DFF * Dd, Dd,
            b2 + (size_t)l * Dd, p_tmp, nullptr, nullptr, Dd, Dd, DFF, 0, 0);
        addln_kernel<<<Mm / 8, 256>>>(p_tmp, ln2_g + (size_t)l * Dd, ln2_b + (size_t)l * Dd);
    }

    // lm_head: fp16 2-pass (A = x16 hi only, B = fp16 hi/lo)
    conv_x16<<<(Mm * Dd / 4 + 255) / 256, 256>>>();
    gemm_mp<1><<<dim3(Mm / TM, VP / TN), 256, GEMM_SMEM>>>(
        (const __nv_bfloat16*)px16, nullptr, Dd,
        (const __nv_bfloat16*)plmh, (const __nv_bfloat16*)plml, VP,
        lm_b, out, nullptr, nullptr, Vv, Vv, Dd, 0, 0);
}